// round 15
// baseline (speedup 1.0000x reference)
#include <cuda_runtime.h>
#include <cuda_bf16.h>
#include <math.h>
#include <stdint.h>

#define SPAT 65536      // F*T = 256*256
#define KSLICES 32
#define CONV2_SMEM (2*34816 + 4*8704)        // A hi/lo + 4-stage B = 104448
#define SC2_SMEM  (2*8*6144)                 // 2 stages x 8 tiles x (128 rows x 48B) = 98304

// ---------------- scratch (device globals; no allocation allowed) ----------------
__device__ __nv_bfloat16 g_yhi[16777216];    // conv intermediate hi [(b*128+o)][s]
__device__ __nv_bfloat16 g_ylo[16777216];    // conv intermediate lo
__device__ __nv_bfloat16 g_qhi[16777216];    // score operands [bp:4][row:256][k:16384]
__device__ __nv_bfloat16 g_qlo[16777216];
__device__ __nv_bfloat16 g_khi[16777216];
__device__ __nv_bfloat16 g_klo[16777216];
__device__ __nv_bfloat16 g_vhi[16777216];    // normalized V bf16 hi/lo
__device__ __nv_bfloat16 g_vlo[16777216];
__device__ __nv_bfloat16 g_pshi[16777216];   // split inputs P
__device__ __nv_bfloat16 g_pslo[16777216];
__device__ __nv_bfloat16 g_qshi[16777216];   // split inputs Q
__device__ __nv_bfloat16 g_qslo[16777216];
__device__ __nv_bfloat16 g_ahi[2*256*256];   // softmax hi/lo [b][m][n]
__device__ __nv_bfloat16 g_alo[2*256*256];
__device__ __nv_bfloat16 g_wc[6*2*16384];    // combined weights [j][hl][o][cc]
__device__ float g_part[1024*256];           // conv stats partials
__device__ float g_srp[KSLICES*2*256*256];   // partial sr [slice][b][m][n]
__device__ float g_sip[KSLICES*2*256*256];
__device__ float g_scale6[6*128];
__device__ float g_shift6[6*128];

// ================= mma.sync / cp.async helpers ===================================
__device__ __forceinline__ void ldm4(uint32_t* r, uint32_t addr) {
    asm volatile("ldmatrix.sync.aligned.m8n8.x4.shared.b16 {%0,%1,%2,%3}, [%4];"
                 : "=r"(r[0]), "=r"(r[1]), "=r"(r[2]), "=r"(r[3]) : "r"(addr));
}
__device__ __forceinline__ void ldm4t(uint32_t* r, uint32_t addr) {
    asm volatile("ldmatrix.sync.aligned.m8n8.x4.trans.shared.b16 {%0,%1,%2,%3}, [%4];"
                 : "=r"(r[0]), "=r"(r[1]), "=r"(r[2]), "=r"(r[3]) : "r"(addr));
}
__device__ __forceinline__ void mma16816(float* c, const uint32_t* a,
                                         uint32_t b0, uint32_t b1) {
    asm volatile(
        "mma.sync.aligned.m16n8k16.row.col.f32.bf16.bf16.f32 "
        "{%0,%1,%2,%3}, {%4,%5,%6,%7}, {%8,%9}, {%0,%1,%2,%3};"
        : "+f"(c[0]), "+f"(c[1]), "+f"(c[2]), "+f"(c[3])
        : "r"(a[0]), "r"(a[1]), "r"(a[2]), "r"(a[3]), "r"(b0), "r"(b1));
}
#define CPA16(sa, gp)  asm volatile("cp.async.cg.shared.global [%0], [%1], 16;" :: "r"(sa), "l"(gp))
#define CPA_COMMIT()   asm volatile("cp.async.commit_group;" ::: "memory")
#define CPA_WAIT(n)    asm volatile("cp.async.wait_group %0;" :: "n"(n) : "memory")

__device__ __forceinline__ uint32_t pack2(float a, float b) {
    __nv_bfloat16 ha = __float2bfloat16_rn(a);
    __nv_bfloat16 hb = __float2bfloat16_rn(b);
    return (uint32_t)__bfloat16_as_ushort(ha) | ((uint32_t)__bfloat16_as_ushort(hb) << 16);
}
__device__ __forceinline__ float bf_hi(float v) {
    return __bfloat162float(__float2bfloat16_rn(v));
}

// ---------------- split input fp32 -> bf16 hi/lo ---------------------------------
__global__ void __launch_bounds__(256) split_kernel(const float* __restrict__ X,
                                                    __nv_bfloat16* __restrict__ hi,
                                                    __nv_bfloat16* __restrict__ lo)
{
    size_t i = ((size_t)blockIdx.x*256 + threadIdx.x) * 4;
    float4 v = *(const float4*)(X + i);
    uint2 h, l;
    h.x = pack2(v.x, v.y); h.y = pack2(v.z, v.w);
    l.x = pack2(v.x - bf_hi(v.x), v.y - bf_hi(v.y));
    l.y = pack2(v.z - bf_hi(v.z), v.w - bf_hi(v.w));
    *(uint2*)(hi + i) = h;
    *(uint2*)(lo + i) = l;
}

// ---------------- build combined complex weight matrices (bf16 hi/lo) ------------
__global__ void __launch_bounds__(256) wcomb_kernel(const float* __restrict__ W6,
                                                    __nv_bfloat16* __restrict__ wc)
{
    const int j = blockIdx.y;
    const int idx = blockIdx.x*256 + threadIdx.x;
    const int o = idx & 127, cc = idx >> 7;
    const float* Wr = W6 + (size_t)(j*2 + 0)*4096;
    const float* Wi = W6 + (size_t)(j*2 + 1)*4096;
    const int oc = (o & 63)*64 + (cc & 63);
    float val;
    if (o < 64) val = (cc < 64) ?  Wr[oc] : -Wi[oc];
    else        val = (cc < 64) ?  Wi[oc] :  Wr[oc];
    float h = bf_hi(val);
    wc[(size_t)j*32768 + o*128 + cc]         = __float2bfloat16_rn(h);
    wc[(size_t)j*32768 + 16384 + o*128 + cc] = __float2bfloat16_rn(val - h);
}

// ---------------- tensor-core conv: 4-stage pipeline, bf16 hi/lo output ----------
__global__ void __launch_bounds__(256) conv_mma_kernel(
    const __nv_bfloat16* __restrict__ Xhi, const __nv_bfloat16* __restrict__ Xlo,
    const __nv_bfloat16* __restrict__ Wc,
    __nv_bfloat16* __restrict__ Yhi, __nv_bfloat16* __restrict__ Ylo,
    float* __restrict__ part)
{
    extern __shared__ char smb[];
    __shared__ float stats_s[2][128][2];
    const uint32_t sb = (uint32_t)__cvta_generic_to_shared(smb);
    const int tid = threadIdx.x, wid = tid >> 5, lane = tid & 31;
    const int b = blockIdx.y, s0 = blockIdx.x * 128;
    const int warp_m = (wid >> 1) * 32, warp_n = (wid & 1) * 64;
    const int cta = blockIdx.y*512 + blockIdx.x;

    for (int i = tid; i < 4096; i += 256) {
        int hl = i >> 11, rem = i & 2047;
        int row = rem >> 4, u = rem & 15;
        uint4 v = *(const uint4*)(Wc + hl*16384 + row*128 + u*8);
        *(uint4*)(smb + hl*34816 + row*272 + u*16) = v;
    }

    const __nv_bfloat16* xh = Xhi + (size_t)b*8388608 + s0;
    const __nv_bfloat16* xl = Xlo + (size_t)b*8388608 + s0;

    auto issueB = [&](int c, int d) {
        #pragma unroll
        for (int i = 0; i < 2; i++) {
            int idx = tid + i*256;
            int hl = idx >> 8, rem = idx & 255;
            int kk = rem >> 4, u = rem & 15;
            const __nv_bfloat16* gp = (hl ? xl : xh) + (size_t)(c*16 + kk)*SPAT + u*8;
            CPA16(sb + 69632 + d*8704 + hl*4352 + kk*272 + u*16, gp);
        }
        CPA_COMMIT();
    };

    float acc[2][8][4];
    #pragma unroll
    for (int fm = 0; fm < 2; fm++)
        #pragma unroll
        for (int fn = 0; fn < 8; fn++)
            #pragma unroll
            for (int u = 0; u < 4; u++) acc[fm][fn][u] = 0.f;

    const int a_row = (lane & 7) + ((lane >> 3) & 1) * 8;
    const int a_u   = lane >> 4;
    const int bt_row = (lane & 7) + ((lane >> 3) & 1) * 8;
    const int bt_c   = (lane >> 4) * 8;

    issueB(0, 0); issueB(1, 1); issueB(2, 2);
    #pragma unroll
    for (int c = 0; c < 8; c++) {
        __syncthreads();
        if (c < 5) issueB(c+3, (c+3) & 3);
        if (c < 5)       { CPA_WAIT(3); }
        else if (c == 5) { CPA_WAIT(2); }
        else if (c == 6) { CPA_WAIT(1); }
        else             { CPA_WAIT(0); }
        __syncthreads();
        const uint32_t bbase = sb + 69632 + (c & 3)*8704;

        uint32_t Ah[2][4], Al[2][4];
        #pragma unroll
        for (int fm = 0; fm < 2; fm++) {
            uint32_t arow_off = (warp_m + fm*16 + a_row)*272 + c*32 + a_u*16;
            ldm4(Ah[fm], sb + arow_off);
            ldm4(Al[fm], sb + 34816 + arow_off);
        }
        uint32_t Bh[8][2], Bl[8][2];
        #pragma unroll
        for (int fn2 = 0; fn2 < 4; fn2++) {
            uint32_t boff = bt_row*272 + (warp_n + fn2*16 + bt_c)*2;
            uint32_t r[4];
            ldm4t(r, bbase + boff);
            Bh[2*fn2+0][0] = r[0]; Bh[2*fn2+0][1] = r[1];
            Bh[2*fn2+1][0] = r[2]; Bh[2*fn2+1][1] = r[3];
            ldm4t(r, bbase + 4352 + boff);
            Bl[2*fn2+0][0] = r[0]; Bl[2*fn2+0][1] = r[1];
            Bl[2*fn2+1][0] = r[2]; Bl[2*fn2+1][1] = r[3];
        }
        #pragma unroll
        for (int fm = 0; fm < 2; fm++)
            #pragma unroll
            for (int fn = 0; fn < 8; fn++) {
                mma16816(acc[fm][fn], Ah[fm], Bh[fn][0], Bh[fn][1]);
                mma16816(acc[fm][fn], Ah[fm], Bl[fn][0], Bl[fn][1]);
                mma16816(acc[fm][fn], Al[fm], Bh[fn][0], Bh[fn][1]);
            }
    }

    // epilogue: write Y (bf16 hi/lo) + per-channel partial stats
    const int rl = lane >> 2, cl = (lane & 3) * 2;
    __nv_bfloat16* Yhb = Yhi + (size_t)b*8388608;
    __nv_bfloat16* Ylb = Ylo + (size_t)b*8388608;
    float su[2][2] = {}, sq[2][2] = {};
    #pragma unroll
    for (int fm = 0; fm < 2; fm++) {
        int r = warp_m + fm*16 + rl;
        #pragma unroll
        for (int fn = 0; fn < 8; fn++) {
            float* cc4 = acc[fm][fn];
            int ncol = warp_n + fn*8 + cl;
            size_t o0 = (size_t)r*SPAT + s0 + ncol;
            size_t o1 = (size_t)(r+8)*SPAT + s0 + ncol;
            *(uint32_t*)(Yhb + o0) = pack2(cc4[0], cc4[1]);
            *(uint32_t*)(Ylb + o0) = pack2(cc4[0] - bf_hi(cc4[0]), cc4[1] - bf_hi(cc4[1]));
            *(uint32_t*)(Yhb + o1) = pack2(cc4[2], cc4[3]);
            *(uint32_t*)(Ylb + o1) = pack2(cc4[2] - bf_hi(cc4[2]), cc4[3] - bf_hi(cc4[3]));
            su[fm][0] += cc4[0] + cc4[1];
            sq[fm][0] += cc4[0]*cc4[0] + cc4[1]*cc4[1];
            su[fm][1] += cc4[2] + cc4[3];
            sq[fm][1] += cc4[2]*cc4[2] + cc4[3]*cc4[3];
        }
    }
    #pragma unroll
    for (int d = 1; d < 4; d <<= 1)
        #pragma unroll
        for (int fm = 0; fm < 2; fm++)
            #pragma unroll
            for (int h = 0; h < 2; h++) {
                su[fm][h] += __shfl_xor_sync(0xFFFFFFFF, su[fm][h], d);
                sq[fm][h] += __shfl_xor_sync(0xFFFFFFFF, sq[fm][h], d);
            }
    if ((lane & 3) == 0) {
        #pragma unroll
        for (int fm = 0; fm < 2; fm++)
            #pragma unroll
            for (int h = 0; h < 2; h++) {
                int row = warp_m + fm*16 + rl + h*8;
                stats_s[wid & 1][row][0] = su[fm][h];
                stats_s[wid & 1][row][1] = sq[fm][h];
            }
    }
    __syncthreads();
    {
        int row = tid >> 1, cp = tid & 1;
        part[(size_t)cta*256 + tid] = stats_s[0][row][cp] + stats_s[1][row][cp];
    }
}

// ---------------- reduce conv partials -> BN scale/shift -------------------------
__global__ void __launch_bounds__(256) stats_reduce_kernel(const float* __restrict__ part,
                                                           const float* __restrict__ g_all,
                                                           const float* __restrict__ beta_all,
                                                           int j,
                                                           float* __restrict__ scale6,
                                                           float* __restrict__ shift6)
{
    __shared__ double ssum[256];
    __shared__ double ssq[256];
    const int pc = blockIdx.x, tid = threadIdx.x;
    double s = 0.0, q = 0.0;
    for (int c = tid; c < 1024; c += 256) {
        s += (double)part[(size_t)c*256 + pc*2];
        q += (double)part[(size_t)c*256 + pc*2 + 1];
    }
    ssum[tid] = s; ssq[tid] = q; __syncthreads();
    for (int st = 128; st > 0; st >>= 1) {
        if (tid < st) { ssum[tid] += ssum[tid+st]; ssq[tid] += ssq[tid+st]; }
        __syncthreads();
    }
    if (tid == 0) {
        double n   = 2.0 * SPAT;
        double mu  = ssum[0] / n;
        double var = ssq[0] / n - mu*mu;
        double inv = 1.0 / sqrt(var + 1e-5);
        float gg = g_all[j*128 + pc];
        float bb = beta_all[j*128 + pc];
        scale6[j*128 + pc] = (float)(gg * inv);
        shift6[j*128 + pc] = bb - (float)(mu * gg * inv);
    }
}

// ---------------- V convert: norm + leaky + bf16 split (reads Y hi/lo) -----------
__global__ void __launch_bounds__(256) vconvert_kernel(const __nv_bfloat16* __restrict__ Yhi,
                                                       const __nv_bfloat16* __restrict__ Ylo,
                                                       __nv_bfloat16* __restrict__ hi,
                                                       __nv_bfloat16* __restrict__ lo,
                                                       const float* __restrict__ sc6,
                                                       const float* __restrict__ sh6,
                                                       int j)
{
    size_t i = ((size_t)blockIdx.x*256 + threadIdx.x) * 4;
    int ch = (int)((i >> 16) & 127);
    float sc = sc6[j*128 + ch], sh = sh6[j*128 + ch];
    uint2 hv = *(const uint2*)(Yhi + i);
    uint2 lv = *(const uint2*)(Ylo + i);
    const __nv_bfloat162* h2 = (const __nv_bfloat162*)&hv;
    const __nv_bfloat162* l2 = (const __nv_bfloat162*)&lv;
    float a0 = __bfloat162float(h2[0].x) + __bfloat162float(l2[0].x);
    float a1 = __bfloat162float(h2[0].y) + __bfloat162float(l2[0].y);
    float a2 = __bfloat162float(h2[1].x) + __bfloat162float(l2[1].x);
    float a3 = __bfloat162float(h2[1].y) + __bfloat162float(l2[1].y);
    a0 = a0*sc + sh; a1 = a1*sc + sh; a2 = a2*sc + sh; a3 = a3*sc + sh;
    a0 = fmaxf(a0, 0.01f*a0); a1 = fmaxf(a1, 0.01f*a1);
    a2 = fmaxf(a2, 0.01f*a2); a3 = fmaxf(a3, 0.01f*a3);
    uint2 h, l;
    h.x = pack2(a0, a1); h.y = pack2(a2, a3);
    l.x = pack2(a0 - bf_hi(a0), a1 - bf_hi(a1));
    l.y = pack2(a2 - bf_hi(a2), a3 - bf_hi(a3));
    *(uint2*)(hi + i) = h;
    *(uint2*)(lo + i) = l;
}

// ---------------- freq-branch convert: norm+leaky+split, NO transpose ------------
__global__ void __launch_bounds__(256) convert_noT_kernel(const __nv_bfloat16* __restrict__ Yhi,
                                                          const __nv_bfloat16* __restrict__ Ylo,
                                                          __nv_bfloat16* __restrict__ hi,
                                                          __nv_bfloat16* __restrict__ lo,
                                                          const float* __restrict__ sc6,
                                                          const float* __restrict__ sh6,
                                                          int j)
{
    const int plane = blockIdx.y;
    const int pc = plane & 127;
    const float sc = sc6[j*128 + pc], sh = sh6[j*128 + pc];
    const int b = plane >> 7, p = (plane >> 6) & 1, c = plane & 63;
    const int bp = b*2 + p;
    const int e0 = (blockIdx.x*256 + threadIdx.x) * 8;
    const int f = e0 >> 8, t = e0 & 255;

    uint4 hv = *(const uint4*)(Yhi + (size_t)plane*SPAT + e0);
    uint4 lv = *(const uint4*)(Ylo + (size_t)plane*SPAT + e0);
    const __nv_bfloat162* h2 = (const __nv_bfloat162*)&hv;
    const __nv_bfloat162* l2 = (const __nv_bfloat162*)&lv;
    float v[8];
    #pragma unroll
    for (int u = 0; u < 4; u++) {
        v[2*u]   = __bfloat162float(h2[u].x) + __bfloat162float(l2[u].x);
        v[2*u+1] = __bfloat162float(h2[u].y) + __bfloat162float(l2[u].y);
    }
    uint32_t wh[4], wl[4];
    #pragma unroll
    for (int u = 0; u < 4; u++) {
        float a = v[2*u]*sc + sh;   a = fmaxf(a, 0.01f*a);
        float bvv = v[2*u+1]*sc + sh; bvv = fmaxf(bvv, 0.01f*bvv);
        wh[u] = pack2(a, bvv);
        wl[u] = pack2(a - bf_hi(a), bvv - bf_hi(bvv));
    }
    size_t ob = ((size_t)(bp*256 + f))*16384 + c*256 + t;
    *(uint4*)(hi + ob) = make_uint4(wh[0],wh[1],wh[2],wh[3]);
    *(uint4*)(lo + ob) = make_uint4(wl[0],wl[1],wl[2],wl[3]);
}

// ---------------- time-branch convert: norm+leaky+split + f/t transpose ----------
__global__ void __launch_bounds__(256) convert_T_kernel(const __nv_bfloat16* __restrict__ Yhi,
                                                        const __nv_bfloat16* __restrict__ Ylo,
                                                        __nv_bfloat16* __restrict__ hi,
                                                        __nv_bfloat16* __restrict__ lo,
                                                        const float* __restrict__ sc6,
                                                        const float* __restrict__ sh6,
                                                        int j)
{
    __shared__ float smt[32][33];
    const int plane = blockIdx.z;
    const int pc = plane & 127;
    const float sc = sc6[j*128 + pc], sh = sh6[j*128 + pc];
    const int f0 = blockIdx.x*32, t0 = blockIdx.y*32;
    const int tid = threadIdx.x;
    const int tx = tid & 31, ty = tid >> 5;
    const size_t pb = (size_t)plane*SPAT;
    #pragma unroll
    for (int jj = 0; jj < 4; jj++) {
        size_t off = pb + (size_t)(f0 + ty + 8*jj)*256 + t0 + tx;
        float v = __bfloat162float(Yhi[off]) + __bfloat162float(Ylo[off]);
        v = v*sc + sh;
        v = fmaxf(v, 0.01f*v);
        smt[ty + 8*jj][tx] = v;
    }
    __syncthreads();
    const int b = plane >> 7, p = (plane >> 6) & 1, c = plane & 63;
    const int bp = b*2 + p;
    const int half = tid >> 7;
    const int idx  = tid & 127;
    const int tt = idx >> 2, fg = idx & 3;
    float v[8];
    #pragma unroll
    for (int u = 0; u < 8; u++) v[u] = smt[fg*8 + u][tt];
    size_t ob = ((size_t)(bp*256 + t0 + tt))*16384 + c*256 + f0 + fg*8;
    if (half == 0) {
        uint32_t w[4];
        #pragma unroll
        for (int u = 0; u < 4; u++) w[u] = pack2(v[2*u], v[2*u+1]);
        *(uint4*)(hi + ob) = make_uint4(w[0],w[1],w[2],w[3]);
    } else {
        uint32_t w[4];
        #pragma unroll
        for (int u = 0; u < 4; u++)
            w[u] = pack2(v[2*u] - bf_hi(v[2*u]), v[2*u+1] - bf_hi(v[2*u+1]));
        *(uint4*)(lo + ob) = make_uint4(w[0],w[1],w[2],w[3]);
    }
}

// ---------------- mma.sync score kernel: 2-stage cp.async, 16-k chunks (R12) -----
__global__ void __launch_bounds__(256) score_mma_kernel(
    const __nv_bfloat16* __restrict__ khi_, const __nv_bfloat16* __restrict__ klo_,
    const __nv_bfloat16* __restrict__ qhi_, const __nv_bfloat16* __restrict__ qlo_,
    float* __restrict__ srp, float* __restrict__ sip)
{
    extern __shared__ char smc[];
    const uint32_t smem_base = (uint32_t)__cvta_generic_to_shared(smc);
    const int tid = threadIdx.x, wid = tid >> 5, lane = tid & 31;
    const int m0 = blockIdx.x * 128, n0 = blockIdx.y * 128;
    const int b = blockIdx.z >> 5, sl = blockIdx.z & 31;
    const int warp_m = (wid >> 1) * 32, warp_n = (wid & 1) * 64;

    const size_t PL = (size_t)256 * 16384;
    const __nv_bfloat16* srcs[8] = {
        khi_ + (size_t)(b*2+0)*PL + (size_t)m0*16384,
        klo_ + (size_t)(b*2+0)*PL + (size_t)m0*16384,
        khi_ + (size_t)(b*2+1)*PL + (size_t)m0*16384,
        klo_ + (size_t)(b*2+1)*PL + (size_t)m0*16384,
        qhi_ + (size_t)(b*2+0)*PL + (size_t)n0*16384,
        qlo_ + (size_t)(b*2+0)*PL + (size_t)n0*16384,
        qhi_ + (size_t)(b*2+1)*PL + (size_t)n0*16384,
        qlo_ + (size_t)(b*2+1)*PL + (size_t)n0*16384
    };

    float acc[2][2][8][4];
    #pragma unroll
    for (int p = 0; p < 2; p++)
        #pragma unroll
        for (int fm = 0; fm < 2; fm++)
            #pragma unroll
            for (int fn = 0; fn < 8; fn++)
                #pragma unroll
                for (int u = 0; u < 4; u++) acc[p][fm][fn][u] = 0.f;

    const int a_row = (lane & 7) + ((lane >> 3) & 1) * 8;
    const int a_uoff = lane >> 4;
    const int b_row = (lane & 7) + ((lane >> 4) << 3);
    const int b_uoff = (lane >> 3) & 1;

    const int kbase = sl * 512;
    auto issueS = [&](int ch, int d) {
        const int k0 = kbase + ch*16;
        #pragma unroll
        for (int i = 0; i < 8; i++) {
            int idx = tid + i*256;
            int t = idx >> 8, rem = idx & 255;
            int row = rem >> 1, u = rem & 1;
            CPA16(smem_base + d*49152 + t*6144 + row*48 + u*16,
                  srcs[t] + (size_t)row*16384 + k0 + u*8);
        }
        CPA_COMMIT();
    };

    issueS(0, 0);
    for (int ch = 0; ch < 32; ch++) {
        if (ch < 31) { issueS(ch+1, (ch+1) & 1); CPA_WAIT(1); }
        else         { CPA_WAIT(0); }
        __syncthreads();
        const uint32_t cb = smem_base + (ch & 1)*49152;

        uint32_t afr[4][2][4];
        #pragma unroll
        for (int t = 0; t < 4; t++)
            #pragma unroll
            for (int fm = 0; fm < 2; fm++)
                ldm4(afr[t][fm], cb + t*6144
                     + (warp_m + fm*16 + a_row)*48 + a_uoff*16);
        uint32_t nKI[2][2][4];
        #pragma unroll
        for (int hl = 0; hl < 2; hl++)
            #pragma unroll
            for (int fm = 0; fm < 2; fm++)
                #pragma unroll
                for (int u = 0; u < 4; u++)
                    nKI[hl][fm][u] = afr[2+hl][fm][u] ^ 0x80008000u;

        #pragma unroll
        for (int qop = 0; qop < 4; qop++) {
            uint32_t bfr[8][2];
            #pragma unroll
            for (int pn = 0; pn < 4; pn++) {
                uint32_t r[4];
                ldm4(r, cb + (4+qop)*6144
                     + (warp_n + pn*16 + b_row)*48 + b_uoff*16);
                bfr[2*pn+0][0] = r[0]; bfr[2*pn+0][1] = r[1];
                bfr[2*pn+1][0] = r[2]; bfr[2*pn+1][1] = r[3];
            }
            #pragma unroll
            for (int fm = 0; fm < 2; fm++)
                #pragma unroll
                for (int fn = 0; fn < 8; fn++) {
                    uint32_t b0 = bfr[fn][0], b1 = bfr[fn][1];
                    if (qop == 0) {
                        mma16816(acc[0][fm][fn], afr[0][fm], b0, b1);
                        mma16816(acc[0][fm][fn], afr[1][fm], b0, b1);
                        mma16816(acc[1][fm][fn], nKI[0][fm], b0, b1);
                        mma16816(acc[1][fm][fn], nKI[1][fm], b0, b1);
                    } else if (qop == 1) {
                        mma16816(acc[0][fm][fn], afr[0][fm], b0, b1);
                        mma16816(acc[1][fm][fn], nKI[0][fm], b0, b1);
                    } else if (qop == 2) {
                        mma16816(acc[0][fm][fn], afr[2][fm], b0, b1);
                        mma16816(acc[0][fm][fn], afr[3][fm], b0, b1);
                        mma16816(acc[1][fm][fn], afr[0][fm], b0, b1);
                        mma16816(acc[1][fm][fn], afr[1][fm], b0, b1);
                    } else {
                        mma16816(acc[0][fm][fn], afr[2][fm], b0, b1);
                        mma16816(acc[1][fm][fn], afr[0][fm], b0, b1);
                    }
                }
        }
        __syncthreads();
    }

    const int rl = lane >> 2, cl = (lane & 3) * 2;
    #pragma unroll
    for (int fm = 0; fm < 2; fm++)
        #pragma unroll
        for (int fn = 0; fn < 8; fn++) {
            int m = m0 + warp_m + fm*16 + rl;
            int n = n0 + warp_n + fn*8 + cl;
            size_t off = (((size_t)sl*2 + b)*256 + m)*256 + n;
            float* c0 = acc[0][fm][fn];
            float* c1 = acc[1][fm][fn];
            *(float2*)(srp + off)         = make_float2(c0[0], c0[1]);
            *(float2*)(srp + off + 8*256) = make_float2(c0[2], c0[3]);
            *(float2*)(sip + off)         = make_float2(c1[0], c1[1]);
            *(float2*)(sip + off + 8*256) = make_float2(c1[2], c1[3]);
        }
}

// ---------------- softmax over query axis n, emits bf16 hi/lo --------------------
__global__ void __launch_bounds__(256) softmax_kernel(const float* __restrict__ srp,
                                                      const float* __restrict__ sip,
                                                      __nv_bfloat16* __restrict__ ahi,
                                                      __nv_bfloat16* __restrict__ alo)
{
    __shared__ float red[256];
    const int bm = blockIdx.x;
    const int b = bm >> 8, m = bm & 255;
    const int n = threadIdx.x;
    float sr = 0.f, si = 0.f;
    for (int sl = 0; sl < KSLICES; sl++) {
        size_t off = (((size_t)sl*2 + b)*256 + m)*256 + n;
        sr += srp[off]; si += sip[off];
    }
    float z = sqrtf(sr*sr + si*si);
    red[n] = z; __syncthreads();
    for (int st = 128; st > 0; st >>= 1) {
        if (n < st) red[n] = fmaxf(red[n], red[n+st]);
        __syncthreads();
    }
    float mx = red[0]; __syncthreads();
    float e = expf(z - mx);
    red[n] = e; __syncthreads();
    for (int st = 128; st > 0; st >>= 1) {
        if (n < st) red[n] += red[n+st];
        __syncthreads();
    }
    float a = e / red[0];
    float h = bf_hi(a);
    size_t off = ((size_t)b*256 + m)*256 + n;
    ahi[off] = __float2bfloat16_rn(h);
    alo[off] = __float2bfloat16_rn(a - h);
}

// ---------------- time-branch output (mma.sync split-3) --------------------------
__global__ void __launch_bounds__(256) out_time_mma_kernel(
    const __nv_bfloat16* __restrict__ vhi, const __nv_bfloat16* __restrict__ vlo,
    const __nv_bfloat16* __restrict__ ahi, const __nv_bfloat16* __restrict__ alo,
    float* __restrict__ out)
{
    __shared__ __align__(16) char sm[37888];
    const uint32_t sb = (uint32_t)__cvta_generic_to_shared(sm);
    const int tid = threadIdx.x, wid = tid >> 5, lane = tid & 31;
    const int r0 = blockIdx.x*128, n0 = blockIdx.y*128, b = blockIdx.z;
    const int warp_m = (wid >> 1) * 32, warp_n = (wid & 1) * 64;

    float acc[2][8][4];
    #pragma unroll
    for (int fm = 0; fm < 2; fm++)
        #pragma unroll
        for (int fn = 0; fn < 8; fn++)
            #pragma unroll
            for (int u = 0; u < 4; u++) acc[fm][fn][u] = 0.f;

    const int a_row = (lane & 7) + ((lane >> 3) & 1) * 8;
    const int a_u   = lane >> 4;
    const int bt_row = (lane & 7) + ((lane >> 3) & 1) * 8;
    const int bt_c   = (lane >> 4) * 8;

    for (int ch = 0; ch < 8; ch++) {
        const int m0c = ch*32;
        __syncthreads();
        #pragma unroll
        for (int i = 0; i < 4; i++) {
            int idx = tid + i*256;
            int hl = idx >> 9, rem = idx & 511;
            int row = rem >> 2, u = rem & 3;
            uint4 v = *(const uint4*)((hl ? vlo : vhi)
                        + (size_t)(b*32768 + r0 + row)*256 + m0c + u*8);
            *(uint4*)(sm + hl*10240 + row*80 + u*16) = v;
        }
        #pragma unroll
        for (int i = 0; i < 4; i++) {
            int idx = tid + i*256;
            int hl = idx >> 9, rem = idx & 511;
            int kk = rem >> 4, u = rem & 15;
            uint4 v = *(const uint4*)((hl ? alo : ahi)
                        + (size_t)(b*256 + m0c + kk)*256 + n0 + u*8);
            *(uint4*)(sm + 20480 + hl*8704 + kk*272 + u*16) = v;
        }
        __syncthreads();
        #pragma unroll
        for (int ks = 0; ks < 2; ks++) {
            uint32_t Vf[2][2][4];
            #pragma unroll
            for (int hl = 0; hl < 2; hl++)
                #pragma unroll
                for (int fm = 0; fm < 2; fm++)
                    ldm4(Vf[hl][fm], sb + hl*10240
                         + (warp_m + fm*16 + a_row)*80 + (ks*2 + a_u)*16);
            uint32_t Af[2][8][2];
            #pragma unroll
            for (int hl = 0; hl < 2; hl++)
                #pragma unroll
                for (int fn2 = 0; fn2 < 4; fn2++) {
                    uint32_t r[4];
                    ldm4t(r, sb + 20480 + hl*8704
                          + (ks*16 + bt_row)*272 + (warp_n + fn2*16 + bt_c)*2);
                    Af[hl][2*fn2+0][0] = r[0]; Af[hl][2*fn2+0][1] = r[1];
                    Af[hl][2*fn2+1][0] = r[2]; Af[hl][2*fn2+1][1] = r[3];
                }
            #pragma unroll
            for (int fm = 0; fm < 2; fm++)
                #pragma unroll
                for (int fn = 0; fn < 8; fn++) {
                    mma16816(acc[fm][fn], Vf[0][fm], Af[0][fn][0], Af[0][fn][1]);
                    mma16816(acc[fm][fn], Vf[0][fm], Af[1][fn][0], Af[1][fn][1]);
                    mma16816(acc[fm][fn], Vf[1][fm], Af[0][fn][0], Af[0][fn][1]);
                }
        }
    }
    const int rl = lane >> 2, cl = (lane & 3) * 2;
    #pragma unroll
    for (int fm = 0; fm < 2; fm++)
        #pragma unroll
        for (int fn = 0; fn < 8; fn++) {
            int r = r0 + warp_m + fm*16 + rl;
            int n = n0 + warp_n + fn*8 + cl;
            float* c4 = acc[fm][fn];
            *(float2*)(out + (size_t)(b*32768 + r)*256 + n)     = make_float2(c4[0], c4[1]);
            *(float2*)(out + (size_t)(b*32768 + r + 8)*256 + n) = make_float2(c4[2], c4[3]);
        }
}

// ---------------- freq-branch output (mma.sync split-3, accumulate) --------------
__global__ void __launch_bounds__(256) out_freq_mma_kernel(
    const __nv_bfloat16* __restrict__ vhi, const __nv_bfloat16* __restrict__ vlo,
    const __nv_bfloat16* __restrict__ ahi, const __nv_bfloat16* __restrict__ alo,
    float* __restrict__ out)
{
    __shared__ __align__(16) char sm[34816];
    const uint32_t sb = (uint32_t)__cvta_generic_to_shared(sm);
    const int tid = threadIdx.x, wid = tid >> 5, lane = tid & 31;
    const int f0 = (blockIdx.x >> 1)*128, t0 = (blockIdx.x & 1)*128;
    const int plane = blockIdx.y, b = plane >> 7;
    const int warp_f = (wid >> 1) * 32, warp_t = (wid & 1) * 64;
    const size_t vbase = (size_t)plane * SPAT;

    float acc[2][8][4];
    #pragma unroll
    for (int fm = 0; fm < 2; fm++)
        #pragma unroll
        for (int fn = 0; fn < 8; fn++)
            #pragma unroll
            for (int u = 0; u < 4; u++) acc[fm][fn][u] = 0.f;

    const int at_row = (lane & 7) + ((lane >> 4) << 3);
    const int at_c   = ((lane >> 3) & 1) * 8;
    const int bt_row = (lane & 7) + ((lane >> 3) & 1) * 8;
    const int bt_c   = (lane >> 4) * 8;

    for (int ch = 0; ch < 8; ch++) {
        const int m0c = ch*32;
        __syncthreads();
        #pragma unroll
        for (int i = 0; i < 4; i++) {
            int idx = tid + i*256;
            int hl = idx >> 9, rem = idx & 511;
            int kk = rem >> 4, u = rem & 15;
            uint4 v = *(const uint4*)((hl ? alo : ahi)
                        + (size_t)(b*256 + m0c + kk)*256 + f0 + u*8);
            *(uint4*)(sm + hl*8704 + kk*272 + u*16) = v;
        }
        #pragma unroll
        for (int i = 0; i < 4; i++) {
            int idx = tid + i*256;
            int hl = idx >> 9, rem = idx & 511;
            int kk = rem >> 4, u = rem & 15;
            uint4 v = *(const uint4*)((hl ? vlo : vhi)
                        + vbase + (size_t)(m0c + kk)*256 + t0 + u*8);
            *(uint4*)(sm + 17408 + hl*8704 + kk*272 + u*16) = v;
        }
        __syncthreads();
        #pragma unroll
        for (int ks = 0; ks < 2; ks++) {
            uint32_t Afr[2][2][4];
            #pragma unroll
            for (int hl = 0; hl < 2; hl++)
                #pragma unroll
                for (int fm = 0; fm < 2; fm++)
                    ldm4t(Afr[hl][fm], sb + hl*8704
                          + (ks*16 + at_row)*272 + (warp_f + fm*16 + at_c)*2);
            uint32_t Vfr[2][8][2];
            #pragma unroll
            for (int hl = 0; hl < 2; hl++)
                #pragma unroll
                for (int fn2 = 0; fn2 < 4; fn2++) {
                    uint32_t r[4];
                    ldm4t(r, sb + 17408 + hl*8704
                          + (ks*16 + bt_row)*272 + (warp_t + fn2*16 + bt_c)*2);
                    Vfr[hl][2*fn2+0][0] = r[0]; Vfr[hl][2*fn2+0][1] = r[1];
                    Vfr[hl][2*fn2+1][0] = r[2]; Vfr[hl][2*fn2+1][1] = r[3];
                }
            #pragma unroll
            for (int fm = 0; fm < 2; fm++)
                #pragma unroll
                for (int fn = 0; fn < 8; fn++) {
                    mma16816(acc[fm][fn], Afr[0][fm], Vfr[0][fn][0], Vfr[0][fn][1]);
                    mma16816(acc[fm][fn], Afr[0][fm], Vfr[1][fn][0], Vfr[1][fn][1]);
                    mma16816(acc[fm][fn], Afr[1][fm], Vfr[0][fn][0], Vfr[0][fn][1]);
                }
        }
    }
    const int rl = lane >> 2, cl = (lane & 3) * 2;
    #pragma unroll
    for (int fm = 0; fm < 2; fm++)
        #pragma unroll
        for (int fn = 0; fn < 8; fn++) {
            int f = f0 + warp_f + fm*16 + rl;
            int t = t0 + warp_t + fn*8 + cl;
            float* c4 = acc[fm][fn];
            float* d0 = out + vbase + (size_t)f*256 + t;
            float* d1 = out + vbase + (size_t)(f + 8)*256 + t;
            float2 o0 = *(float2*)d0, o1 = *(float2*)d1;
            o0.x += c4[0]; o0.y += c4[1];
            o1.x += c4[2]; o1.y += c4[3];
            *(float2*)d0 = o0; *(float2*)d1 = o1;
        }
}

// ---------------- host launch ----------------------------------------------------
extern "C" void kernel_launch(void* const* d_in, const int* in_sizes, int n_in,
                              void* d_out, int out_size)
{
    const float* P    = (const float*)d_in[0];
    const float* Q    = (const float*)d_in[1];
    const float* W    = (const float*)d_in[2];
    // d_in[3] = bias: cancels exactly under BN mean subtraction -> unused
    const float* g    = (const float*)d_in[4];
    const float* beta = (const float*)d_in[5];
    float* out = (float*)d_out;

    float *srp, *sip, *scp, *shp, *partp;
    __nv_bfloat16 *yhi, *ylo, *qhi, *qlo, *khi, *klo, *vhi, *vlo,
                  *pshi, *pslo, *qshi, *qslo, *ahip, *alop, *wcp;
    cudaGetSymbolAddress((void**)&yhi, g_yhi);
    cudaGetSymbolAddress((void**)&ylo, g_ylo);
    cudaGetSymbolAddress((void**)&qhi, g_qhi);
    cudaGetSymbolAddress((void**)&qlo, g_qlo);
    cudaGetSymbolAddress((void**)&khi, g_khi);
    cudaGetSymbolAddress((void**)&klo, g_klo);
    cudaGetSymbolAddress((void**)&vhi, g_vhi);
    cudaGetSymbolAddress((void**)&vlo, g_vlo);
    cudaGetSymbolAddress((void**)&pshi, g_pshi);
    cudaGetSymbolAddress((void**)&pslo, g_pslo);
    cudaGetSymbolAddress((void**)&qshi, g_qshi);
    cudaGetSymbolAddress((void**)&qslo, g_qslo);
    cudaGetSymbolAddress((void**)&ahip, g_ahi);
    cudaGetSymbolAddress((void**)&alop, g_alo);
    cudaGetSymbolAddress((void**)&wcp, g_wc);
    cudaGetSymbolAddress((void**)&partp, g_part);
    cudaGetSymbolAddress((void**)&srp, g_srp);
    cudaGetSymbolAddress((void**)&sip, g_sip);
    cudaGetSymbolAddress((void**)&scp, g_scale6);
    cudaGetSymbolAddress((void**)&shp, g_shift6);

    cudaFuncSetAttribute(conv_mma_kernel, cudaFuncAttributeMaxDynamicSharedMemorySize, CONV2_SMEM);
    cudaFuncSetAttribute(score_mma_kernel, cudaFuncAttributeMaxDynamicSharedMemorySize, SC2_SMEM);

    // one-time prep
    split_kernel<<<16384, 256>>>(P, pshi, pslo);
    split_kernel<<<16384, 256>>>(Q, qshi, qslo);
    wcomb_kernel<<<dim3(64, 6), 256>>>(W, wcp);

    auto conv_stats = [&](const __nv_bfloat16* xhi, const __nv_bfloat16* xlo, int j) {
        conv_mma_kernel<<<dim3(512, 2), 256, CONV2_SMEM>>>(
            xhi, xlo, wcp + (size_t)j*32768, yhi, ylo, partp);
        stats_reduce_kernel<<<128, 256>>>(partp, g, beta, j, scp, shp);
    };

    // ---- time branch ----
    conv_stats(qshi, qslo, 0);
    convert_T_kernel<<<dim3(8, 8, 256), 256>>>(yhi, ylo, qhi, qlo, scp, shp, 0);
    conv_stats(pshi, pslo, 1);
    convert_T_kernel<<<dim3(8, 8, 256), 256>>>(yhi, ylo, khi, klo, scp, shp, 1);
    conv_stats(pshi, pslo, 2);
    vconvert_kernel<<<16384, 256>>>(yhi, ylo, vhi, vlo, scp, shp, 2);
    score_mma_kernel<<<dim3(2, 2, 64), 256, SC2_SMEM>>>(khi, klo, qhi, qlo, srp, sip);
    softmax_kernel<<<512, 256>>>(srp, sip, ahip, alop);
    out_time_mma_kernel<<<dim3(256, 2, 2), 256>>>(vhi, vlo, ahip, alop, out);

    // ---- freq branch ----
    conv_stats(qshi, qslo, 3);
    convert_noT_kernel<<<dim3(32, 256), 256>>>(yhi, ylo, qhi, qlo, scp, shp, 3);
    conv_stats(pshi, pslo, 4);
    convert_noT_kernel<<<dim3(32, 256), 256>>>(yhi, ylo, khi, klo, scp, shp, 4);
    conv_stats(pshi, pslo, 5);
    vconvert_kernel<<<16384, 256>>>(yhi, ylo, vhi, vlo, scp, shp, 5);
    score_mma_kernel<<<dim3(2, 2, 64), 256, SC2_SMEM>>>(khi, klo, qhi, qlo, srp, sip);
    softmax_kernel<<<512, 256>>>(srp, sip, ahip, alop);
    out_freq_mma_kernel<<<dim3(4, 256), 256>>>(vhi, vlo, ahip, alop, out);
}

// round 16
// speedup vs baseline: 1.0924x; 1.0924x over previous
#include <cuda_runtime.h>
#include <cuda_bf16.h>
#include <math.h>
#include <stdint.h>

#define SPAT 65536      // F*T = 256*256
#define KSLICES 32
#define CONV2_SMEM (2*34816 + 4*8704)        // A hi/lo + 4-stage B = 104448
#define SC2_SMEM  (2*8*6144)                 // 2 stages x 8 tiles x (128 rows x 48B) = 98304

// ---------------- scratch (device globals; no allocation allowed) ----------------
__device__ float g_q[16777216];
__device__ float g_k[16777216];
__device__ float g_v[16777216];
__device__ __nv_bfloat16 g_qhi[16777216];    // score operands [bp:4][row:256][k:16384]
__device__ __nv_bfloat16 g_qlo[16777216];
__device__ __nv_bfloat16 g_khi[16777216];
__device__ __nv_bfloat16 g_klo[16777216];
__device__ __nv_bfloat16 g_vhi[16777216];    // normalized V bf16 hi/lo
__device__ __nv_bfloat16 g_vlo[16777216];
__device__ __nv_bfloat16 g_pshi[16777216];   // split inputs P
__device__ __nv_bfloat16 g_pslo[16777216];
__device__ __nv_bfloat16 g_qshi[16777216];   // split inputs Q
__device__ __nv_bfloat16 g_qslo[16777216];
__device__ __nv_bfloat16 g_ahi[2*256*256];   // softmax hi/lo [b][m][n]
__device__ __nv_bfloat16 g_alo[2*256*256];
__device__ __nv_bfloat16 g_wc[6*2*16384];    // combined weights [j][hl][o][cc]
__device__ float g_part[1024*256];           // conv stats partials
__device__ float g_srp[KSLICES*2*256*256];   // partial sr [slice][b][m][n]
__device__ float g_sip[KSLICES*2*256*256];
__device__ float g_scale6[6*128];
__device__ float g_shift6[6*128];

// ================= mma.sync / cp.async helpers ===================================
__device__ __forceinline__ void ldm4(uint32_t* r, uint32_t addr) {
    asm volatile("ldmatrix.sync.aligned.m8n8.x4.shared.b16 {%0,%1,%2,%3}, [%4];"
                 : "=r"(r[0]), "=r"(r[1]), "=r"(r[2]), "=r"(r[3]) : "r"(addr));
}
__device__ __forceinline__ void ldm4t(uint32_t* r, uint32_t addr) {
    asm volatile("ldmatrix.sync.aligned.m8n8.x4.trans.shared.b16 {%0,%1,%2,%3}, [%4];"
                 : "=r"(r[0]), "=r"(r[1]), "=r"(r[2]), "=r"(r[3]) : "r"(addr));
}
__device__ __forceinline__ void mma16816(float* c, const uint32_t* a,
                                         uint32_t b0, uint32_t b1) {
    asm volatile(
        "mma.sync.aligned.m16n8k16.row.col.f32.bf16.bf16.f32 "
        "{%0,%1,%2,%3}, {%4,%5,%6,%7}, {%8,%9}, {%0,%1,%2,%3};"
        : "+f"(c[0]), "+f"(c[1]), "+f"(c[2]), "+f"(c[3])
        : "r"(a[0]), "r"(a[1]), "r"(a[2]), "r"(a[3]), "r"(b0), "r"(b1));
}
#define CPA16(sa, gp)  asm volatile("cp.async.cg.shared.global [%0], [%1], 16;" :: "r"(sa), "l"(gp))
#define CPA_COMMIT()   asm volatile("cp.async.commit_group;" ::: "memory")
#define CPA_WAIT(n)    asm volatile("cp.async.wait_group %0;" :: "n"(n) : "memory")

__device__ __forceinline__ uint32_t pack2(float a, float b) {
    __nv_bfloat16 ha = __float2bfloat16_rn(a);
    __nv_bfloat16 hb = __float2bfloat16_rn(b);
    return (uint32_t)__bfloat16_as_ushort(ha) | ((uint32_t)__bfloat16_as_ushort(hb) << 16);
}
__device__ __forceinline__ float bf_hi(float v) {
    return __bfloat162float(__float2bfloat16_rn(v));
}

// ---------------- split input fp32 -> bf16 hi/lo ---------------------------------
__global__ void __launch_bounds__(256) split_kernel(const float* __restrict__ X,
                                                    __nv_bfloat16* __restrict__ hi,
                                                    __nv_bfloat16* __restrict__ lo)
{
    size_t i = ((size_t)blockIdx.x*256 + threadIdx.x) * 4;
    float4 v = *(const float4*)(X + i);
    uint2 h, l;
    h.x = pack2(v.x, v.y); h.y = pack2(v.z, v.w);
    l.x = pack2(v.x - bf_hi(v.x), v.y - bf_hi(v.y));
    l.y = pack2(v.z - bf_hi(v.z), v.w - bf_hi(v.w));
    *(uint2*)(hi + i) = h;
    *(uint2*)(lo + i) = l;
}

// ---------------- build combined complex weight matrices (bf16 hi/lo) ------------
__global__ void __launch_bounds__(256) wcomb_kernel(const float* __restrict__ W6,
                                                    __nv_bfloat16* __restrict__ wc)
{
    const int j = blockIdx.y;
    const int idx = blockIdx.x*256 + threadIdx.x;
    const int o = idx & 127, cc = idx >> 7;
    const float* Wr = W6 + (size_t)(j*2 + 0)*4096;
    const float* Wi = W6 + (size_t)(j*2 + 1)*4096;
    const int oc = (o & 63)*64 + (cc & 63);
    float val;
    if (o < 64) val = (cc < 64) ?  Wr[oc] : -Wi[oc];
    else        val = (cc < 64) ?  Wi[oc] :  Wr[oc];
    float h = bf_hi(val);
    wc[(size_t)j*32768 + o*128 + cc]         = __float2bfloat16_rn(h);
    wc[(size_t)j*32768 + 16384 + o*128 + cc] = __float2bfloat16_rn(val - h);
}

// ---------------- tensor-core conv: 4-stage cp.async pipeline, chunks of 16 k ----
__global__ void __launch_bounds__(256) conv_mma_kernel(
    const __nv_bfloat16* __restrict__ Xhi, const __nv_bfloat16* __restrict__ Xlo,
    const __nv_bfloat16* __restrict__ Wc,
    float* __restrict__ Y, float* __restrict__ part)
{
    extern __shared__ char smb[];
    __shared__ float stats_s[2][128][2];
    const uint32_t sb = (uint32_t)__cvta_generic_to_shared(smb);
    const int tid = threadIdx.x, wid = tid >> 5, lane = tid & 31;
    const int b = blockIdx.y, s0 = blockIdx.x * 128;
    const int warp_m = (wid >> 1) * 32, warp_n = (wid & 1) * 64;
    const int cta = blockIdx.y*512 + blockIdx.x;

    for (int i = tid; i < 4096; i += 256) {
        int hl = i >> 11, rem = i & 2047;
        int row = rem >> 4, u = rem & 15;
        uint4 v = *(const uint4*)(Wc + hl*16384 + row*128 + u*8);
        *(uint4*)(smb + hl*34816 + row*272 + u*16) = v;
    }

    const __nv_bfloat16* xh = Xhi + (size_t)b*8388608 + s0;
    const __nv_bfloat16* xl = Xlo + (size_t)b*8388608 + s0;

    auto issueB = [&](int c, int d) {
        #pragma unroll
        for (int i = 0; i < 2; i++) {
            int idx = tid + i*256;
            int hl = idx >> 8, rem = idx & 255;
            int kk = rem >> 4, u = rem & 15;
            const __nv_bfloat16* gp = (hl ? xl : xh) + (size_t)(c*16 + kk)*SPAT + u*8;
            CPA16(sb + 69632 + d*8704 + hl*4352 + kk*272 + u*16, gp);
        }
        CPA_COMMIT();
    };

    float acc[2][8][4];
    #pragma unroll
    for (int fm = 0; fm < 2; fm++)
        #pragma unroll
        for (int fn = 0; fn < 8; fn++)
            #pragma unroll
            for (int u = 0; u < 4; u++) acc[fm][fn][u] = 0.f;

    const int a_row = (lane & 7) + ((lane >> 3) & 1) * 8;
    const int a_u   = lane >> 4;
    const int bt_row = (lane & 7) + ((lane >> 3) & 1) * 8;
    const int bt_c   = (lane >> 4) * 8;

    issueB(0, 0); issueB(1, 1); issueB(2, 2);
    #pragma unroll
    for (int c = 0; c < 8; c++) {
        __syncthreads();
        if (c < 5) issueB(c+3, (c+3) & 3);
        if (c < 5)       { CPA_WAIT(3); }
        else if (c == 5) { CPA_WAIT(2); }
        else if (c == 6) { CPA_WAIT(1); }
        else             { CPA_WAIT(0); }
        __syncthreads();
        const uint32_t bbase = sb + 69632 + (c & 3)*8704;

        uint32_t Ah[2][4], Al[2][4];
        #pragma unroll
        for (int fm = 0; fm < 2; fm++) {
            uint32_t arow_off = (warp_m + fm*16 + a_row)*272 + c*32 + a_u*16;
            ldm4(Ah[fm], sb + arow_off);
            ldm4(Al[fm], sb + 34816 + arow_off);
        }
        uint32_t Bh[8][2], Bl[8][2];
        #pragma unroll
        for (int fn2 = 0; fn2 < 4; fn2++) {
            uint32_t boff = bt_row*272 + (warp_n + fn2*16 + bt_c)*2;
            uint32_t r[4];
            ldm4t(r, bbase + boff);
            Bh[2*fn2+0][0] = r[0]; Bh[2*fn2+0][1] = r[1];
            Bh[2*fn2+1][0] = r[2]; Bh[2*fn2+1][1] = r[3];
            ldm4t(r, bbase + 4352 + boff);
            Bl[2*fn2+0][0] = r[0]; Bl[2*fn2+0][1] = r[1];
            Bl[2*fn2+1][0] = r[2]; Bl[2*fn2+1][1] = r[3];
        }
        #pragma unroll
        for (int fm = 0; fm < 2; fm++)
            #pragma unroll
            for (int fn = 0; fn < 8; fn++) {
                mma16816(acc[fm][fn], Ah[fm], Bh[fn][0], Bh[fn][1]);
                mma16816(acc[fm][fn], Ah[fm], Bl[fn][0], Bl[fn][1]);
                mma16816(acc[fm][fn], Al[fm], Bh[fn][0], Bh[fn][1]);
            }
    }

    // epilogue: write Y + per-channel partial stats
    const int rl = lane >> 2, cl = (lane & 3) * 2;
    float* Yb = Y + (size_t)b*8388608;
    float su[2][2] = {}, sq[2][2] = {};
    #pragma unroll
    for (int fm = 0; fm < 2; fm++) {
        int r = warp_m + fm*16 + rl;
        #pragma unroll
        for (int fn = 0; fn < 8; fn++) {
            float* cc4 = acc[fm][fn];
            int ncol = warp_n + fn*8 + cl;
            *(float2*)(Yb + (size_t)r*SPAT + s0 + ncol)     = make_float2(cc4[0], cc4[1]);
            *(float2*)(Yb + (size_t)(r+8)*SPAT + s0 + ncol) = make_float2(cc4[2], cc4[3]);
            su[fm][0] += cc4[0] + cc4[1];
            sq[fm][0] += cc4[0]*cc4[0] + cc4[1]*cc4[1];
            su[fm][1] += cc4[2] + cc4[3];
            sq[fm][1] += cc4[2]*cc4[2] + cc4[3]*cc4[3];
        }
    }
    #pragma unroll
    for (int d = 1; d < 4; d <<= 1)
        #pragma unroll
        for (int fm = 0; fm < 2; fm++)
            #pragma unroll
            for (int h = 0; h < 2; h++) {
                su[fm][h] += __shfl_xor_sync(0xFFFFFFFF, su[fm][h], d);
                sq[fm][h] += __shfl_xor_sync(0xFFFFFFFF, sq[fm][h], d);
            }
    if ((lane & 3) == 0) {
        #pragma unroll
        for (int fm = 0; fm < 2; fm++)
            #pragma unroll
            for (int h = 0; h < 2; h++) {
                int row = warp_m + fm*16 + rl + h*8;
                stats_s[wid & 1][row][0] = su[fm][h];
                stats_s[wid & 1][row][1] = sq[fm][h];
            }
    }
    __syncthreads();
    {
        int row = tid >> 1, cp = tid & 1;
        part[(size_t)cta*256 + tid] = stats_s[0][row][cp] + stats_s[1][row][cp];
    }
}

// ---------------- reduce conv partials -> BN scale/shift -------------------------
__global__ void __launch_bounds__(256) stats_reduce_kernel(const float* __restrict__ part,
                                                           const float* __restrict__ g_all,
                                                           const float* __restrict__ beta_all,
                                                           int j,
                                                           float* __restrict__ scale6,
                                                           float* __restrict__ shift6)
{
    __shared__ double ssum[256];
    __shared__ double ssq[256];
    const int pc = blockIdx.x, tid = threadIdx.x;
    double s = 0.0, q = 0.0;
    for (int c = tid; c < 1024; c += 256) {
        s += (double)part[(size_t)c*256 + pc*2];
        q += (double)part[(size_t)c*256 + pc*2 + 1];
    }
    ssum[tid] = s; ssq[tid] = q; __syncthreads();
    for (int st = 128; st > 0; st >>= 1) {
        if (tid < st) { ssum[tid] += ssum[tid+st]; ssq[tid] += ssq[tid+st]; }
        __syncthreads();
    }
    if (tid == 0) {
        double n   = 2.0 * SPAT;
        double mu  = ssum[0] / n;
        double var = ssq[0] / n - mu*mu;
        double inv = 1.0 / sqrt(var + 1e-5);
        float gg = g_all[j*128 + pc];
        float bb = beta_all[j*128 + pc];
        scale6[j*128 + pc] = (float)(gg * inv);
        shift6[j*128 + pc] = bb - (float)(mu * gg * inv);
    }
}

// ---------------- V convert: norm + leaky + bf16 split ---------------------------
__global__ void __launch_bounds__(256) vconvert_kernel(const float* __restrict__ Y,
                                                       __nv_bfloat16* __restrict__ hi,
                                                       __nv_bfloat16* __restrict__ lo,
                                                       const float* __restrict__ sc6,
                                                       const float* __restrict__ sh6,
                                                       int j)
{
    size_t i = ((size_t)blockIdx.x*256 + threadIdx.x) * 4;
    int ch = (int)((i >> 16) & 127);
    float sc = sc6[j*128 + ch], sh = sh6[j*128 + ch];
    float4 v = *(const float4*)(Y + i);
    float a0 = v.x*sc + sh, a1 = v.y*sc + sh, a2 = v.z*sc + sh, a3 = v.w*sc + sh;
    a0 = fmaxf(a0, 0.01f*a0); a1 = fmaxf(a1, 0.01f*a1);
    a2 = fmaxf(a2, 0.01f*a2); a3 = fmaxf(a3, 0.01f*a3);
    uint2 h, l;
    h.x = pack2(a0, a1); h.y = pack2(a2, a3);
    l.x = pack2(a0 - bf_hi(a0), a1 - bf_hi(a1));
    l.y = pack2(a2 - bf_hi(a2), a3 - bf_hi(a3));
    *(uint2*)(hi + i) = h;
    *(uint2*)(lo + i) = l;
}

// ---------------- freq-branch convert: norm+leaky+split, NO transpose ------------
__global__ void __launch_bounds__(256) convert_noT_kernel(const float* __restrict__ Y,
                                                          __nv_bfloat16* __restrict__ hi,
                                                          __nv_bfloat16* __restrict__ lo,
                                                          const float* __restrict__ sc6,
                                                          const float* __restrict__ sh6,
                                                          int j)
{
    const int plane = blockIdx.y;
    const int pc = plane & 127;
    const float sc = sc6[j*128 + pc], sh = sh6[j*128 + pc];
    const int b = plane >> 7, p = (plane >> 6) & 1, c = plane & 63;
    const int bp = b*2 + p;
    const int e0 = (blockIdx.x*256 + threadIdx.x) * 8;
    const int f = e0 >> 8, t = e0 & 255;

    const float* ip = Y + (size_t)plane*SPAT + e0;
    float4 v0 = *(const float4*)ip;
    float4 v1 = *(const float4*)(ip + 4);
    float v[8] = {v0.x,v0.y,v0.z,v0.w,v1.x,v1.y,v1.z,v1.w};
    uint32_t wh[4], wl[4];
    #pragma unroll
    for (int u = 0; u < 4; u++) {
        float a = v[2*u]*sc + sh;   a = fmaxf(a, 0.01f*a);
        float bvv = v[2*u+1]*sc + sh; bvv = fmaxf(bvv, 0.01f*bvv);
        wh[u] = pack2(a, bvv);
        wl[u] = pack2(a - bf_hi(a), bvv - bf_hi(bvv));
    }
    size_t ob = ((size_t)(bp*256 + f))*16384 + c*256 + t;
    *(uint4*)(hi + ob) = make_uint4(wh[0],wh[1],wh[2],wh[3]);
    *(uint4*)(lo + ob) = make_uint4(wl[0],wl[1],wl[2],wl[3]);
}

// ---------------- time-branch convert: norm+leaky+split + f/t transpose ----------
__global__ void __launch_bounds__(256) convert_T_kernel(const float* __restrict__ Y,
                                                        __nv_bfloat16* __restrict__ hi,
                                                        __nv_bfloat16* __restrict__ lo,
                                                        const float* __restrict__ sc6,
                                                        const float* __restrict__ sh6,
                                                        int j)
{
    __shared__ float smt[32][33];
    const int plane = blockIdx.z;
    const int pc = plane & 127;
    const float sc = sc6[j*128 + pc], sh = sh6[j*128 + pc];
    const int f0 = blockIdx.x*32, t0 = blockIdx.y*32;
    const int tid = threadIdx.x;
    const int tx = tid & 31, ty = tid >> 5;
    const float* ip = Y + (size_t)plane*SPAT;
    #pragma unroll
    for (int jj = 0; jj < 4; jj++) {
        float v = ip[(size_t)(f0 + ty + 8*jj)*256 + t0 + tx];
        v = v*sc + sh;
        v = fmaxf(v, 0.01f*v);
        smt[ty + 8*jj][tx] = v;
    }
    __syncthreads();
    const int b = plane >> 7, p = (plane >> 6) & 1, c = plane & 63;
    const int bp = b*2 + p;
    const int half = tid >> 7;
    const int idx  = tid & 127;
    const int tt = idx >> 2, fg = idx & 3;
    float v[8];
    #pragma unroll
    for (int u = 0; u < 8; u++) v[u] = smt[fg*8 + u][tt];
    size_t ob = ((size_t)(bp*256 + t0 + tt))*16384 + c*256 + f0 + fg*8;
    if (half == 0) {
        uint32_t w[4];
        #pragma unroll
        for (int u = 0; u < 4; u++) w[u] = pack2(v[2*u], v[2*u+1]);
        *(uint4*)(hi + ob) = make_uint4(w[0],w[1],w[2],w[3]);
    } else {
        uint32_t w[4];
        #pragma unroll
        for (int u = 0; u < 4; u++)
            w[u] = pack2(v[2*u] - bf_hi(v[2*u]), v[2*u+1] - bf_hi(v[2*u+1]));
        *(uint4*)(lo + ob) = make_uint4(w[0],w[1],w[2],w[3]);
    }
}

// ---------------- mma.sync score kernel: 2-stage cp.async, 16-k chunks -----------
__global__ void __launch_bounds__(256) score_mma_kernel(
    const __nv_bfloat16* __restrict__ khi_, const __nv_bfloat16* __restrict__ klo_,
    const __nv_bfloat16* __restrict__ qhi_, const __nv_bfloat16* __restrict__ qlo_,
    float* __restrict__ srp, float* __restrict__ sip)
{
    extern __shared__ char smc[];
    const uint32_t smem_base = (uint32_t)__cvta_generic_to_shared(smc);
    const int tid = threadIdx.x, wid = tid >> 5, lane = tid & 31;
    const int m0 = blockIdx.x * 128, n0 = blockIdx.y * 128;
    const int b = blockIdx.z >> 5, sl = blockIdx.z & 31;
    const int warp_m = (wid >> 1) * 32, warp_n = (wid & 1) * 64;

    const size_t PL = (size_t)256 * 16384;
    const __nv_bfloat16* srcs[8] = {
        khi_ + (size_t)(b*2+0)*PL + (size_t)m0*16384,
        klo_ + (size_t)(b*2+0)*PL + (size_t)m0*16384,
        khi_ + (size_t)(b*2+1)*PL + (size_t)m0*16384,
        klo_ + (size_t)(b*2+1)*PL + (size_t)m0*16384,
        qhi_ + (size_t)(b*2+0)*PL + (size_t)n0*16384,
        qlo_ + (size_t)(b*2+0)*PL + (size_t)n0*16384,
        qhi_ + (size_t)(b*2+1)*PL + (size_t)n0*16384,
        qlo_ + (size_t)(b*2+1)*PL + (size_t)n0*16384
    };

    float acc[2][2][8][4];
    #pragma unroll
    for (int p = 0; p < 2; p++)
        #pragma unroll
        for (int fm = 0; fm < 2; fm++)
            #pragma unroll
            for (int fn = 0; fn < 8; fn++)
                #pragma unroll
                for (int u = 0; u < 4; u++) acc[p][fm][fn][u] = 0.f;

    const int a_row = (lane & 7) + ((lane >> 3) & 1) * 8;
    const int a_uoff = lane >> 4;
    const int b_row = (lane & 7) + ((lane >> 4) << 3);
    const int b_uoff = (lane >> 3) & 1;

    const int kbase = sl * 512;
    auto issueS = [&](int ch, int d) {
        const int k0 = kbase + ch*16;
        #pragma unroll
        for (int i = 0; i < 8; i++) {
            int idx = tid + i*256;
            int t = idx >> 8, rem = idx & 255;
            int row = rem >> 1, u = rem & 1;
            CPA16(smem_base + d*49152 + t*6144 + row*48 + u*16,
                  srcs[t] + (size_t)row*16384 + k0 + u*8);
        }
        CPA_COMMIT();
    };

    issueS(0, 0);
    for (int ch = 0; ch < 32; ch++) {
        if (ch < 31) { issueS(ch+1, (ch+1) & 1); CPA_WAIT(1); }
        else         { CPA_WAIT(0); }
        __syncthreads();
        const uint32_t cb = smem_base + (ch & 1)*49152;

        uint32_t afr[4][2][4];
        #pragma unroll
        for (int t = 0; t < 4; t++)
            #pragma unroll
            for (int fm = 0; fm < 2; fm++)
                ldm4(afr[t][fm], cb + t*6144
                     + (warp_m + fm*16 + a_row)*48 + a_uoff*16);
        uint32_t nKI[2][2][4];
        #pragma unroll
        for (int hl = 0; hl < 2; hl++)
            #pragma unroll
            for (int fm = 0; fm < 2; fm++)
                #pragma unroll
                for (int u = 0; u < 4; u++)
                    nKI[hl][fm][u] = afr[2+hl][fm][u] ^ 0x80008000u;

        #pragma unroll
        for (int qop = 0; qop < 4; qop++) {
            uint32_t bfr[8][2];
            #pragma unroll
            for (int pn = 0; pn < 4; pn++) {
                uint32_t r[4];
                ldm4(r, cb + (4+qop)*6144
                     + (warp_n + pn*16 + b_row)*48 + b_uoff*16);
                bfr[2*pn+0][0] = r[0]; bfr[2*pn+0][1] = r[1];
                bfr[2*pn+1][0] = r[2]; bfr[2*pn+1][1] = r[3];
            }
            #pragma unroll
            for (int fm = 0; fm < 2; fm++)
                #pragma unroll
                for (int fn = 0; fn < 8; fn++) {
                    uint32_t b0 = bfr[fn][0], b1 = bfr[fn][1];
                    if (qop == 0) {
                        mma16816(acc[0][fm][fn], afr[0][fm], b0, b1);
                        mma16816(acc[0][fm][fn], afr[1][fm], b0, b1);
                        mma16816(acc[1][fm][fn], nKI[0][fm], b0, b1);
                        mma16816(acc[1][fm][fn], nKI[1][fm], b0, b1);
                    } else if (qop == 1) {
                        mma16816(acc[0][fm][fn], afr[0][fm], b0, b1);
                        mma16816(acc[1][fm][fn], nKI[0][fm], b0, b1);
                    } else if (qop == 2) {
                        mma16816(acc[0][fm][fn], afr[2][fm], b0, b1);
                        mma16816(acc[0][fm][fn], afr[3][fm], b0, b1);
                        mma16816(acc[1][fm][fn], afr[0][fm], b0, b1);
                        mma16816(acc[1][fm][fn], afr[1][fm], b0, b1);
                    } else {
                        mma16816(acc[0][fm][fn], afr[2][fm], b0, b1);
                        mma16816(acc[1][fm][fn], afr[0][fm], b0, b1);
                    }
                }
        }
        __syncthreads();
    }

    const int rl = lane >> 2, cl = (lane & 3) * 2;
    #pragma unroll
    for (int fm = 0; fm < 2; fm++)
        #pragma unroll
        for (int fn = 0; fn < 8; fn++) {
            int m = m0 + warp_m + fm*16 + rl;
            int n = n0 + warp_n + fn*8 + cl;
            size_t off = (((size_t)sl*2 + b)*256 + m)*256 + n;
            float* c0 = acc[0][fm][fn];
            float* c1 = acc[1][fm][fn];
            *(float2*)(srp + off)         = make_float2(c0[0], c0[1]);
            *(float2*)(srp + off + 8*256) = make_float2(c0[2], c0[3]);
            *(float2*)(sip + off)         = make_float2(c1[0], c1[1]);
            *(float2*)(sip + off + 8*256) = make_float2(c1[2], c1[3]);
        }
}

// ---------------- softmax over query axis n, emits bf16 hi/lo --------------------
__global__ void __launch_bounds__(256) softmax_kernel(const float* __restrict__ srp,
                                                      const float* __restrict__ sip,
                                                      __nv_bfloat16* __restrict__ ahi,
                                                      __nv_bfloat16* __restrict__ alo)
{
    __shared__ float red[256];
    const int bm = blockIdx.x;
    const int b = bm >> 8, m = bm & 255;
    const int n = threadIdx.x;
    float sr = 0.f, si = 0.f;
    for (int sl = 0; sl < KSLICES; sl++) {
        size_t off = (((size_t)sl*2 + b)*256 + m)*256 + n;
        sr += srp[off]; si += sip[off];
    }
    float z = sqrtf(sr*sr + si*si);
    red[n] = z; __syncthreads();
    for (int st = 128; st > 0; st >>= 1) {
        if (n < st) red[n] = fmaxf(red[n], red[n+st]);
        __syncthreads();
    }
    float mx = red[0]; __syncthreads();
    float e = expf(z - mx);
    red[n] = e; __syncthreads();
    for (int st = 128; st > 0; st >>= 1) {
        if (n < st) red[n] += red[n+st];
        __syncthreads();
    }
    float a = e / red[0];
    float h = bf_hi(a);
    size_t off = ((size_t)b*256 + m)*256 + n;
    ahi[off] = __float2bfloat16_rn(h);
    alo[off] = __float2bfloat16_rn(a - h);
}

// ---------------- time-branch output (mma.sync split-3) --------------------------
__global__ void __launch_bounds__(256) out_time_mma_kernel(
    const __nv_bfloat16* __restrict__ vhi, const __nv_bfloat16* __restrict__ vlo,
    const __nv_bfloat16* __restrict__ ahi, const __nv_bfloat16* __restrict__ alo,
    float* __restrict__ out)
{
    __shared__ __align__(16) char sm[37888];
    const uint32_t sb = (uint32_t)__cvta_generic_to_shared(sm);
    const int tid = threadIdx.x, wid = tid >> 5, lane = tid & 31;
    const int r0 = blockIdx.x*128, n0 = blockIdx.y*128, b = blockIdx.z;
    const int warp_m = (wid >> 1) * 32, warp_n = (wid & 1) * 64;

    float acc[2][8][4];
    #pragma unroll
    for (int fm = 0; fm < 2; fm++)
        #pragma unroll
        for (int fn = 0; fn < 8; fn++)
            #pragma unroll
            for (int u = 0; u < 4; u++) acc[fm][fn][u] = 0.f;

    const int a_row = (lane & 7) + ((lane >> 3) & 1) * 8;
    const int a_u   = lane >> 4;
    const int bt_row = (lane & 7) + ((lane >> 3) & 1) * 8;
    const int bt_c   = (lane >> 4) * 8;

    for (int ch = 0; ch < 8; ch++) {
        const int m0c = ch*32;
        __syncthreads();
        #pragma unroll
        for (int i = 0; i < 4; i++) {
            int idx = tid + i*256;
            int hl = idx >> 9, rem = idx & 511;
            int row = rem >> 2, u = rem & 3;
            uint4 v = *(const uint4*)((hl ? vlo : vhi)
                        + (size_t)(b*32768 + r0 + row)*256 + m0c + u*8);
            *(uint4*)(sm + hl*10240 + row*80 + u*16) = v;
        }
        #pragma unroll
        for (int i = 0; i < 4; i++) {
            int idx = tid + i*256;
            int hl = idx >> 9, rem = idx & 511;
            int kk = rem >> 4, u = rem & 15;
            uint4 v = *(const uint4*)((hl ? alo : ahi)
                        + (size_t)(b*256 + m0c + kk)*256 + n0 + u*8);
            *(uint4*)(sm + 20480 + hl*8704 + kk*272 + u*16) = v;
        }
        __syncthreads();
        #pragma unroll
        for (int ks = 0; ks < 2; ks++) {
            uint32_t Vf[2][2][4];
            #pragma unroll
            for (int hl = 0; hl < 2; hl++)
                #pragma unroll
                for (int fm = 0; fm < 2; fm++)
                    ldm4(Vf[hl][fm], sb + hl*10240
                         + (warp_m + fm*16 + a_row)*80 + (ks*2 + a_u)*16);
            uint32_t Af[2][8][2];
            #pragma unroll
            for (int hl = 0; hl < 2; hl++)
                #pragma unroll
                for (int fn2 = 0; fn2 < 4; fn2++) {
                    uint32_t r[4];
                    ldm4t(r, sb + 20480 + hl*8704
                          + (ks*16 + bt_row)*272 + (warp_n + fn2*16 + bt_c)*2);
                    Af[hl][2*fn2+0][0] = r[0]; Af[hl][2*fn2+0][1] = r[1];
                    Af[hl][2*fn2+1][0] = r[2]; Af[hl][2*fn2+1][1] = r[3];
                }
            #pragma unroll
            for (int fm = 0; fm < 2; fm++)
                #pragma unroll
                for (int fn = 0; fn < 8; fn++) {
                    mma16816(acc[fm][fn], Vf[0][fm], Af[0][fn][0], Af[0][fn][1]);
                    mma16816(acc[fm][fn], Vf[0][fm], Af[1][fn][0], Af[1][fn][1]);
                    mma16816(acc[fm][fn], Vf[1][fm], Af[0][fn][0], Af[0][fn][1]);
                }
        }
    }
    const int rl = lane >> 2, cl = (lane & 3) * 2;
    #pragma unroll
    for (int fm = 0; fm < 2; fm++)
        #pragma unroll
        for (int fn = 0; fn < 8; fn++) {
            int r = r0 + warp_m + fm*16 + rl;
            int n = n0 + warp_n + fn*8 + cl;
            float* c4 = acc[fm][fn];
            *(float2*)(out + (size_t)(b*32768 + r)*256 + n)     = make_float2(c4[0], c4[1]);
            *(float2*)(out + (size_t)(b*32768 + r + 8)*256 + n) = make_float2(c4[2], c4[3]);
        }
}

// ---------------- freq-branch output (mma.sync split-3, accumulate) --------------
__global__ void __launch_bounds__(256) out_freq_mma_kernel(
    const __nv_bfloat16* __restrict__ vhi, const __nv_bfloat16* __restrict__ vlo,
    const __nv_bfloat16* __restrict__ ahi, const __nv_bfloat16* __restrict__ alo,
    float* __restrict__ out)
{
    __shared__ __align__(16) char sm[34816];
    const uint32_t sb = (uint32_t)__cvta_generic_to_shared(sm);
    const int tid = threadIdx.x, wid = tid >> 5, lane = tid & 31;
    const int f0 = (blockIdx.x >> 1)*128, t0 = (blockIdx.x & 1)*128;
    const int plane = blockIdx.y, b = plane >> 7;
    const int warp_f = (wid >> 1) * 32, warp_t = (wid & 1) * 64;
    const size_t vbase = (size_t)plane * SPAT;

    float acc[2][8][4];
    #pragma unroll
    for (int fm = 0; fm < 2; fm++)
        #pragma unroll
        for (int fn = 0; fn < 8; fn++)
            #pragma unroll
            for (int u = 0; u < 4; u++) acc[fm][fn][u] = 0.f;

    const int at_row = (lane & 7) + ((lane >> 4) << 3);
    const int at_c   = ((lane >> 3) & 1) * 8;
    const int bt_row = (lane & 7) + ((lane >> 3) & 1) * 8;
    const int bt_c   = (lane >> 4) * 8;

    for (int ch = 0; ch < 8; ch++) {
        const int m0c = ch*32;
        __syncthreads();
        #pragma unroll
        for (int i = 0; i < 4; i++) {
            int idx = tid + i*256;
            int hl = idx >> 9, rem = idx & 511;
            int kk = rem >> 4, u = rem & 15;
            uint4 v = *(const uint4*)((hl ? alo : ahi)
                        + (size_t)(b*256 + m0c + kk)*256 + f0 + u*8);
            *(uint4*)(sm + hl*8704 + kk*272 + u*16) = v;
        }
        #pragma unroll
        for (int i = 0; i < 4; i++) {
            int idx = tid + i*256;
            int hl = idx >> 9, rem = idx & 511;
            int kk = rem >> 4, u = rem & 15;
            uint4 v = *(const uint4*)((hl ? vlo : vhi)
                        + vbase + (size_t)(m0c + kk)*256 + t0 + u*8);
            *(uint4*)(sm + 17408 + hl*8704 + kk*272 + u*16) = v;
        }
        __syncthreads();
        #pragma unroll
        for (int ks = 0; ks < 2; ks++) {
            uint32_t Afr[2][2][4];
            #pragma unroll
            for (int hl = 0; hl < 2; hl++)
                #pragma unroll
                for (int fm = 0; fm < 2; fm++)
                    ldm4t(Afr[hl][fm], sb + hl*8704
                          + (ks*16 + at_row)*272 + (warp_f + fm*16 + at_c)*2);
            uint32_t Vfr[2][8][2];
            #pragma unroll
            for (int hl = 0; hl < 2; hl++)
                #pragma unroll
                for (int fn2 = 0; fn2 < 4; fn2++) {
                    uint32_t r[4];
                    ldm4t(r, sb + 17408 + hl*8704
                          + (ks*16 + bt_row)*272 + (warp_t + fn2*16 + bt_c)*2);
                    Vfr[hl][2*fn2+0][0] = r[0]; Vfr[hl][2*fn2+0][1] = r[1];
                    Vfr[hl][2*fn2+1][0] = r[2]; Vfr[hl][2*fn2+1][1] = r[3];
                }
            #pragma unroll
            for (int fm = 0; fm < 2; fm++)
                #pragma unroll
                for (int fn = 0; fn < 8; fn++) {
                    mma16816(acc[fm][fn], Afr[0][fm], Vfr[0][fn][0], Vfr[0][fn][1]);
                    mma16816(acc[fm][fn], Afr[0][fm], Vfr[1][fn][0], Vfr[1][fn][1]);
                    mma16816(acc[fm][fn], Afr[1][fm], Vfr[0][fn][0], Vfr[0][fn][1]);
                }
        }
    }
    const int rl = lane >> 2, cl = (lane & 3) * 2;
    #pragma unroll
    for (int fm = 0; fm < 2; fm++)
        #pragma unroll
        for (int fn = 0; fn < 8; fn++) {
            int f = f0 + warp_f + fm*16 + rl;
            int t = t0 + warp_t + fn*8 + cl;
            float* c4 = acc[fm][fn];
            float* d0 = out + vbase + (size_t)f*256 + t;
            float* d1 = out + vbase + (size_t)(f + 8)*256 + t;
            float2 o0 = *(float2*)d0, o1 = *(float2*)d1;
            o0.x += c4[0]; o0.y += c4[1];
            o1.x += c4[2]; o1.y += c4[3];
            *(float2*)d0 = o0; *(float2*)d1 = o1;
        }
}

// ---------------- host launch ----------------------------------------------------
extern "C" void kernel_launch(void* const* d_in, const int* in_sizes, int n_in,
                              void* d_out, int out_size)
{
    const float* P    = (const float*)d_in[0];
    const float* Q    = (const float*)d_in[1];
    const float* W    = (const float*)d_in[2];
    // d_in[3] = bias: cancels exactly under BN mean subtraction -> unused
    const float* g    = (const float*)d_in[4];
    const float* beta = (const float*)d_in[5];
    float* out = (float*)d_out;

    float *qp, *kp, *vp, *srp, *sip, *scp, *shp, *partp;
    __nv_bfloat16 *qhi, *qlo, *khi, *klo, *vhi, *vlo, *pshi, *pslo, *qshi, *qslo,
                  *ahip, *alop, *wcp;
    cudaGetSymbolAddress((void**)&qp,  g_q);
    cudaGetSymbolAddress((void**)&kp,  g_k);
    cudaGetSymbolAddress((void**)&vp,  g_v);
    cudaGetSymbolAddress((void**)&qhi, g_qhi);
    cudaGetSymbolAddress((void**)&qlo, g_qlo);
    cudaGetSymbolAddress((void**)&khi, g_khi);
    cudaGetSymbolAddress((void**)&klo, g_klo);
    cudaGetSymbolAddress((void**)&vhi, g_vhi);
    cudaGetSymbolAddress((void**)&vlo, g_vlo);
    cudaGetSymbolAddress((void**)&pshi, g_pshi);
    cudaGetSymbolAddress((void**)&pslo, g_pslo);
    cudaGetSymbolAddress((void**)&qshi, g_qshi);
    cudaGetSymbolAddress((void**)&qslo, g_qslo);
    cudaGetSymbolAddress((void**)&ahip, g_ahi);
    cudaGetSymbolAddress((void**)&alop, g_alo);
    cudaGetSymbolAddress((void**)&wcp, g_wc);
    cudaGetSymbolAddress((void**)&partp, g_part);
    cudaGetSymbolAddress((void**)&srp, g_srp);
    cudaGetSymbolAddress((void**)&sip, g_sip);
    cudaGetSymbolAddress((void**)&scp, g_scale6);
    cudaGetSymbolAddress((void**)&shp, g_shift6);

    cudaFuncSetAttribute(conv_mma_kernel, cudaFuncAttributeMaxDynamicSharedMemorySize, CONV2_SMEM);
    cudaFuncSetAttribute(score_mma_kernel, cudaFuncAttributeMaxDynamicSharedMemorySize, SC2_SMEM);

    // one-time prep
    split_kernel<<<16384, 256>>>(P, pshi, pslo);
    split_kernel<<<16384, 256>>>(Q, qshi, qslo);
    wcomb_kernel<<<dim3(64, 6), 256>>>(W, wcp);

    auto conv_stats = [&](const __nv_bfloat16* xhi, const __nv_bfloat16* xlo,
                          int j, float* Y) {
        conv_mma_kernel<<<dim3(512, 2), 256, CONV2_SMEM>>>(xhi, xlo, wcp + (size_t)j*32768, Y, partp);
        stats_reduce_kernel<<<128, 256>>>(partp, g, beta, j, scp, shp);
    };

    // ---- time branch ----
    conv_stats(qshi, qslo, 0, qp);
    convert_T_kernel<<<dim3(8, 8, 256), 256>>>(qp, qhi, qlo, scp, shp, 0);
    conv_stats(pshi, pslo, 1, kp);
    convert_T_kernel<<<dim3(8, 8, 256), 256>>>(kp, khi, klo, scp, shp, 1);
    conv_stats(pshi, pslo, 2, vp);
    vconvert_kernel<<<16384, 256>>>(vp, vhi, vlo, scp, shp, 2);
    score_mma_kernel<<<dim3(2, 2, 64), 256, SC2_SMEM>>>(khi, klo, qhi, qlo, srp, sip);
    softmax_kernel<<<512, 256>>>(srp, sip, ahip, alop);
    out_time_mma_kernel<<<dim3(256, 2, 2), 256>>>(vhi, vlo, ahip, alop, out);

    // ---- freq branch ----
    conv_stats(qshi, qslo, 3, qp);
    convert_noT_kernel<<<dim3(32, 256), 256>>>(qp, qhi, qlo, scp, shp, 3);
    conv_stats(pshi, pslo, 4, kp);
    convert_noT_kernel<<<dim3(32, 256), 256>>>(kp, khi, klo, scp, shp, 4);
    conv_stats(pshi, pslo, 5, vp);
    vconvert_kernel<<<16384, 256>>>(vp, vhi, vlo, scp, shp, 5);
    score_mma_kernel<<<dim3(2, 2, 64), 256, SC2_SMEM>>>(khi, klo, qhi, qlo, srp, sip);
    softmax_kernel<<<512, 256>>>(srp, sip, ahip, alop);
    out_freq_mma_kernel<<<dim3(4, 256), 256>>>(vhi, vlo, ahip, alop, out);
}

// round 17
// speedup vs baseline: 1.0967x; 1.0039x over previous
#include <cuda_runtime.h>
#include <cuda_bf16.h>
#include <math.h>
#include <stdint.h>

#define SPAT 65536      // F*T = 256*256
#define KSLICES 32
#define CONV2_SMEM (2*34816 + 4*8704)        // A hi/lo + 4-stage B = 104448
#define SC2_SMEM  (2*8*6144)                 // 2 stages x 8 tiles x (128 rows x 48B) = 98304

// ---------------- scratch (device globals; no allocation allowed) ----------------
__device__ float g_q[16777216];
__device__ float g_k[16777216];
__device__ float g_v[16777216];
__device__ __nv_bfloat16 g_qhi[16777216];    // score operands [bp:4][row:256][k:16384]
__device__ __nv_bfloat16 g_qlo[16777216];
__device__ __nv_bfloat16 g_khi[16777216];
__device__ __nv_bfloat16 g_klo[16777216];
__device__ __nv_bfloat16 g_vhi[16777216];    // normalized V bf16 hi/lo
__device__ __nv_bfloat16 g_vlo[16777216];
__device__ __nv_bfloat16 g_pshi[16777216];   // split inputs P
__device__ __nv_bfloat16 g_pslo[16777216];
__device__ __nv_bfloat16 g_qshi[16777216];   // split inputs Q
__device__ __nv_bfloat16 g_qslo[16777216];
__device__ __nv_bfloat16 g_ahi[2*256*256];   // softmax hi/lo [b][m][n]
__device__ __nv_bfloat16 g_alo[2*256*256];
__device__ __nv_bfloat16 g_wc[6*2*16384];    // combined weights [j][hl][o][cc]
__device__ float g_part[3*1024*256];         // conv stats partials, 3 chain slices
__device__ float g_srp[KSLICES*2*256*256];   // partial sr [slice][b][m][n]
__device__ float g_sip[KSLICES*2*256*256];
__device__ float g_scale6[6*128];
__device__ float g_shift6[6*128];

// ================= mma.sync / cp.async helpers ===================================
__device__ __forceinline__ void ldm4(uint32_t* r, uint32_t addr) {
    asm volatile("ldmatrix.sync.aligned.m8n8.x4.shared.b16 {%0,%1,%2,%3}, [%4];"
                 : "=r"(r[0]), "=r"(r[1]), "=r"(r[2]), "=r"(r[3]) : "r"(addr));
}
__device__ __forceinline__ void ldm4t(uint32_t* r, uint32_t addr) {
    asm volatile("ldmatrix.sync.aligned.m8n8.x4.trans.shared.b16 {%0,%1,%2,%3}, [%4];"
                 : "=r"(r[0]), "=r"(r[1]), "=r"(r[2]), "=r"(r[3]) : "r"(addr));
}
__device__ __forceinline__ void mma16816(float* c, const uint32_t* a,
                                         uint32_t b0, uint32_t b1) {
    asm volatile(
        "mma.sync.aligned.m16n8k16.row.col.f32.bf16.bf16.f32 "
        "{%0,%1,%2,%3}, {%4,%5,%6,%7}, {%8,%9}, {%0,%1,%2,%3};"
        : "+f"(c[0]), "+f"(c[1]), "+f"(c[2]), "+f"(c[3])
        : "r"(a[0]), "r"(a[1]), "r"(a[2]), "r"(a[3]), "r"(b0), "r"(b1));
}
#define CPA16(sa, gp)  asm volatile("cp.async.cg.shared.global [%0], [%1], 16;" :: "r"(sa), "l"(gp))
#define CPA_COMMIT()   asm volatile("cp.async.commit_group;" ::: "memory")
#define CPA_WAIT(n)    asm volatile("cp.async.wait_group %0;" :: "n"(n) : "memory")

__device__ __forceinline__ uint32_t pack2(float a, float b) {
    __nv_bfloat16 ha = __float2bfloat16_rn(a);
    __nv_bfloat16 hb = __float2bfloat16_rn(b);
    return (uint32_t)__bfloat16_as_ushort(ha) | ((uint32_t)__bfloat16_as_ushort(hb) << 16);
}
__device__ __forceinline__ float bf_hi(float v) {
    return __bfloat162float(__float2bfloat16_rn(v));
}

// ---------------- split input fp32 -> bf16 hi/lo ---------------------------------
__global__ void __launch_bounds__(256) split_kernel(const float* __restrict__ X,
                                                    __nv_bfloat16* __restrict__ hi,
                                                    __nv_bfloat16* __restrict__ lo)
{
    size_t i = ((size_t)blockIdx.x*256 + threadIdx.x) * 4;
    float4 v = *(const float4*)(X + i);
    uint2 h, l;
    h.x = pack2(v.x, v.y); h.y = pack2(v.z, v.w);
    l.x = pack2(v.x - bf_hi(v.x), v.y - bf_hi(v.y));
    l.y = pack2(v.z - bf_hi(v.z), v.w - bf_hi(v.w));
    *(uint2*)(hi + i) = h;
    *(uint2*)(lo + i) = l;
}

// ---------------- build combined complex weight matrices (bf16 hi/lo) ------------
__global__ void __launch_bounds__(256) wcomb_kernel(const float* __restrict__ W6,
                                                    __nv_bfloat16* __restrict__ wc)
{
    const int j = blockIdx.y;
    const int idx = blockIdx.x*256 + threadIdx.x;
    const int o = idx & 127, cc = idx >> 7;
    const float* Wr = W6 + (size_t)(j*2 + 0)*4096;
    const float* Wi = W6 + (size_t)(j*2 + 1)*4096;
    const int oc = (o & 63)*64 + (cc & 63);
    float val;
    if (o < 64) val = (cc < 64) ?  Wr[oc] : -Wi[oc];
    else        val = (cc < 64) ?  Wi[oc] :  Wr[oc];
    float h = bf_hi(val);
    wc[(size_t)j*32768 + o*128 + cc]         = __float2bfloat16_rn(h);
    wc[(size_t)j*32768 + 16384 + o*128 + cc] = __float2bfloat16_rn(val - h);
}

// ---------------- tensor-core conv: 4-stage cp.async pipeline, chunks of 16 k ----
__global__ void __launch_bounds__(256) conv_mma_kernel(
    const __nv_bfloat16* __restrict__ Xhi, const __nv_bfloat16* __restrict__ Xlo,
    const __nv_bfloat16* __restrict__ Wc,
    float* __restrict__ Y, float* __restrict__ part)
{
    extern __shared__ char smb[];
    __shared__ float stats_s[2][128][2];
    const uint32_t sb = (uint32_t)__cvta_generic_to_shared(smb);
    const int tid = threadIdx.x, wid = tid >> 5, lane = tid & 31;
    const int b = blockIdx.y, s0 = blockIdx.x * 128;
    const int warp_m = (wid >> 1) * 32, warp_n = (wid & 1) * 64;
    const int cta = blockIdx.y*512 + blockIdx.x;

    for (int i = tid; i < 4096; i += 256) {
        int hl = i >> 11, rem = i & 2047;
        int row = rem >> 4, u = rem & 15;
        uint4 v = *(const uint4*)(Wc + hl*16384 + row*128 + u*8);
        *(uint4*)(smb + hl*34816 + row*272 + u*16) = v;
    }

    const __nv_bfloat16* xh = Xhi + (size_t)b*8388608 + s0;
    const __nv_bfloat16* xl = Xlo + (size_t)b*8388608 + s0;

    auto issueB = [&](int c, int d) {
        #pragma unroll
        for (int i = 0; i < 2; i++) {
            int idx = tid + i*256;
            int hl = idx >> 8, rem = idx & 255;
            int kk = rem >> 4, u = rem & 15;
            const __nv_bfloat16* gp = (hl ? xl : xh) + (size_t)(c*16 + kk)*SPAT + u*8;
            CPA16(sb + 69632 + d*8704 + hl*4352 + kk*272 + u*16, gp);
        }
        CPA_COMMIT();
    };

    float acc[2][8][4];
    #pragma unroll
    for (int fm = 0; fm < 2; fm++)
        #pragma unroll
        for (int fn = 0; fn < 8; fn++)
            #pragma unroll
            for (int u = 0; u < 4; u++) acc[fm][fn][u] = 0.f;

    const int a_row = (lane & 7) + ((lane >> 3) & 1) * 8;
    const int a_u   = lane >> 4;
    const int bt_row = (lane & 7) + ((lane >> 3) & 1) * 8;
    const int bt_c   = (lane >> 4) * 8;

    issueB(0, 0); issueB(1, 1); issueB(2, 2);
    #pragma unroll
    for (int c = 0; c < 8; c++) {
        __syncthreads();
        if (c < 5) issueB(c+3, (c+3) & 3);
        if (c < 5)       { CPA_WAIT(3); }
        else if (c == 5) { CPA_WAIT(2); }
        else if (c == 6) { CPA_WAIT(1); }
        else             { CPA_WAIT(0); }
        __syncthreads();
        const uint32_t bbase = sb + 69632 + (c & 3)*8704;

        uint32_t Ah[2][4], Al[2][4];
        #pragma unroll
        for (int fm = 0; fm < 2; fm++) {
            uint32_t arow_off = (warp_m + fm*16 + a_row)*272 + c*32 + a_u*16;
            ldm4(Ah[fm], sb + arow_off);
            ldm4(Al[fm], sb + 34816 + arow_off);
        }
        uint32_t Bh[8][2], Bl[8][2];
        #pragma unroll
        for (int fn2 = 0; fn2 < 4; fn2++) {
            uint32_t boff = bt_row*272 + (warp_n + fn2*16 + bt_c)*2;
            uint32_t r[4];
            ldm4t(r, bbase + boff);
            Bh[2*fn2+0][0] = r[0]; Bh[2*fn2+0][1] = r[1];
            Bh[2*fn2+1][0] = r[2]; Bh[2*fn2+1][1] = r[3];
            ldm4t(r, bbase + 4352 + boff);
            Bl[2*fn2+0][0] = r[0]; Bl[2*fn2+0][1] = r[1];
            Bl[2*fn2+1][0] = r[2]; Bl[2*fn2+1][1] = r[3];
        }
        #pragma unroll
        for (int fm = 0; fm < 2; fm++)
            #pragma unroll
            for (int fn = 0; fn < 8; fn++) {
                mma16816(acc[fm][fn], Ah[fm], Bh[fn][0], Bh[fn][1]);
                mma16816(acc[fm][fn], Ah[fm], Bl[fn][0], Bl[fn][1]);
                mma16816(acc[fm][fn], Al[fm], Bh[fn][0], Bh[fn][1]);
            }
    }

    // epilogue: write Y + per-channel partial stats
    const int rl = lane >> 2, cl = (lane & 3) * 2;
    float* Yb = Y + (size_t)b*8388608;
    float su[2][2] = {}, sq[2][2] = {};
    #pragma unroll
    for (int fm = 0; fm < 2; fm++) {
        int r = warp_m + fm*16 + rl;
        #pragma unroll
        for (int fn = 0; fn < 8; fn++) {
            float* cc4 = acc[fm][fn];
            int ncol = warp_n + fn*8 + cl;
            *(float2*)(Yb + (size_t)r*SPAT + s0 + ncol)     = make_float2(cc4[0], cc4[1]);
            *(float2*)(Yb + (size_t)(r+8)*SPAT + s0 + ncol) = make_float2(cc4[2], cc4[3]);
            su[fm][0] += cc4[0] + cc4[1];
            sq[fm][0] += cc4[0]*cc4[0] + cc4[1]*cc4[1];
            su[fm][1] += cc4[2] + cc4[3];
            sq[fm][1] += cc4[2]*cc4[2] + cc4[3]*cc4[3];
        }
    }
    #pragma unroll
    for (int d = 1; d < 4; d <<= 1)
        #pragma unroll
        for (int fm = 0; fm < 2; fm++)
            #pragma unroll
            for (int h = 0; h < 2; h++) {
                su[fm][h] += __shfl_xor_sync(0xFFFFFFFF, su[fm][h], d);
                sq[fm][h] += __shfl_xor_sync(0xFFFFFFFF, sq[fm][h], d);
            }
    if ((lane & 3) == 0) {
        #pragma unroll
        for (int fm = 0; fm < 2; fm++)
            #pragma unroll
            for (int h = 0; h < 2; h++) {
                int row = warp_m + fm*16 + rl + h*8;
                stats_s[wid & 1][row][0] = su[fm][h];
                stats_s[wid & 1][row][1] = sq[fm][h];
            }
    }
    __syncthreads();
    {
        int row = tid >> 1, cp = tid & 1;
        part[(size_t)cta*256 + tid] = stats_s[0][row][cp] + stats_s[1][row][cp];
    }
}

// ---------------- reduce conv partials -> BN scale/shift -------------------------
__global__ void __launch_bounds__(256) stats_reduce_kernel(const float* __restrict__ part,
                                                           const float* __restrict__ g_all,
                                                           const float* __restrict__ beta_all,
                                                           int j,
                                                           float* __restrict__ scale6,
                                                           float* __restrict__ shift6)
{
    __shared__ double ssum[256];
    __shared__ double ssq[256];
    const int pc = blockIdx.x, tid = threadIdx.x;
    double s = 0.0, q = 0.0;
    for (int c = tid; c < 1024; c += 256) {
        s += (double)part[(size_t)c*256 + pc*2];
        q += (double)part[(size_t)c*256 + pc*2 + 1];
    }
    ssum[tid] = s; ssq[tid] = q; __syncthreads();
    for (int st = 128; st > 0; st >>= 1) {
        if (tid < st) { ssum[tid] += ssum[tid+st]; ssq[tid] += ssq[tid+st]; }
        __syncthreads();
    }
    if (tid == 0) {
        double n   = 2.0 * SPAT;
        double mu  = ssum[0] / n;
        double var = ssq[0] / n - mu*mu;
        double inv = 1.0 / sqrt(var + 1e-5);
        float gg = g_all[j*128 + pc];
        float bb = beta_all[j*128 + pc];
        scale6[j*128 + pc] = (float)(gg * inv);
        shift6[j*128 + pc] = bb - (float)(mu * gg * inv);
    }
}

// ---------------- V convert: norm + leaky + bf16 split ---------------------------
__global__ void __launch_bounds__(256) vconvert_kernel(const float* __restrict__ Y,
                                                       __nv_bfloat16* __restrict__ hi,
                                                       __nv_bfloat16* __restrict__ lo,
                                                       const float* __restrict__ sc6,
                                                       const float* __restrict__ sh6,
                                                       int j)
{
    size_t i = ((size_t)blockIdx.x*256 + threadIdx.x) * 4;
    int ch = (int)((i >> 16) & 127);
    float sc = sc6[j*128 + ch], sh = sh6[j*128 + ch];
    float4 v = *(const float4*)(Y + i);
    float a0 = v.x*sc + sh, a1 = v.y*sc + sh, a2 = v.z*sc + sh, a3 = v.w*sc + sh;
    a0 = fmaxf(a0, 0.01f*a0); a1 = fmaxf(a1, 0.01f*a1);
    a2 = fmaxf(a2, 0.01f*a2); a3 = fmaxf(a3, 0.01f*a3);
    uint2 h, l;
    h.x = pack2(a0, a1); h.y = pack2(a2, a3);
    l.x = pack2(a0 - bf_hi(a0), a1 - bf_hi(a1));
    l.y = pack2(a2 - bf_hi(a2), a3 - bf_hi(a3));
    *(uint2*)(hi + i) = h;
    *(uint2*)(lo + i) = l;
}

// ---------------- freq-branch convert: norm+leaky+split, NO transpose ------------
__global__ void __launch_bounds__(256) convert_noT_kernel(const float* __restrict__ Y,
                                                          __nv_bfloat16* __restrict__ hi,
                                                          __nv_bfloat16* __restrict__ lo,
                                                          const float* __restrict__ sc6,
                                                          const float* __restrict__ sh6,
                                                          int j)
{
    const int plane = blockIdx.y;
    const int pc = plane & 127;
    const float sc = sc6[j*128 + pc], sh = sh6[j*128 + pc];
    const int b = plane >> 7, p = (plane >> 6) & 1, c = plane & 63;
    const int bp = b*2 + p;
    const int e0 = (blockIdx.x*256 + threadIdx.x) * 8;
    const int f = e0 >> 8, t = e0 & 255;

    const float* ip = Y + (size_t)plane*SPAT + e0;
    float4 v0 = *(const float4*)ip;
    float4 v1 = *(const float4*)(ip + 4);
    float v[8] = {v0.x,v0.y,v0.z,v0.w,v1.x,v1.y,v1.z,v1.w};
    uint32_t wh[4], wl[4];
    #pragma unroll
    for (int u = 0; u < 4; u++) {
        float a = v[2*u]*sc + sh;   a = fmaxf(a, 0.01f*a);
        float bvv = v[2*u+1]*sc + sh; bvv = fmaxf(bvv, 0.01f*bvv);
        wh[u] = pack2(a, bvv);
        wl[u] = pack2(a - bf_hi(a), bvv - bf_hi(bvv));
    }
    size_t ob = ((size_t)(bp*256 + f))*16384 + c*256 + t;
    *(uint4*)(hi + ob) = make_uint4(wh[0],wh[1],wh[2],wh[3]);
    *(uint4*)(lo + ob) = make_uint4(wl[0],wl[1],wl[2],wl[3]);
}

// ---------------- time-branch convert: norm+leaky+split + f/t transpose ----------
__global__ void __launch_bounds__(256) convert_T_kernel(const float* __restrict__ Y,
                                                        __nv_bfloat16* __restrict__ hi,
                                                        __nv_bfloat16* __restrict__ lo,
                                                        const float* __restrict__ sc6,
                                                        const float* __restrict__ sh6,
                                                        int j)
{
    __shared__ float smt[32][33];
    const int plane = blockIdx.z;
    const int pc = plane & 127;
    const float sc = sc6[j*128 + pc], sh = sh6[j*128 + pc];
    const int f0 = blockIdx.x*32, t0 = blockIdx.y*32;
    const int tid = threadIdx.x;
    const int tx = tid & 31, ty = tid >> 5;
    const float* ip = Y + (size_t)plane*SPAT;
    #pragma unroll
    for (int jj = 0; jj < 4; jj++) {
        float v = ip[(size_t)(f0 + ty + 8*jj)*256 + t0 + tx];
        v = v*sc + sh;
        v = fmaxf(v, 0.01f*v);
        smt[ty + 8*jj][tx] = v;
    }
    __syncthreads();
    const int b = plane >> 7, p = (plane >> 6) & 1, c = plane & 63;
    const int bp = b*2 + p;
    const int half = tid >> 7;
    const int idx  = tid & 127;
    const int tt = idx >> 2, fg = idx & 3;
    float v[8];
    #pragma unroll
    for (int u = 0; u < 8; u++) v[u] = smt[fg*8 + u][tt];
    size_t ob = ((size_t)(bp*256 + t0 + tt))*16384 + c*256 + f0 + fg*8;
    if (half == 0) {
        uint32_t w[4];
        #pragma unroll
        for (int u = 0; u < 4; u++) w[u] = pack2(v[2*u], v[2*u+1]);
        *(uint4*)(hi + ob) = make_uint4(w[0],w[1],w[2],w[3]);
    } else {
        uint32_t w[4];
        #pragma unroll
        for (int u = 0; u < 4; u++)
            w[u] = pack2(v[2*u] - bf_hi(v[2*u]), v[2*u+1] - bf_hi(v[2*u+1]));
        *(uint4*)(lo + ob) = make_uint4(w[0],w[1],w[2],w[3]);
    }
}

// ---------------- mma.sync score kernel: 2-stage cp.async, 16-k chunks -----------
__global__ void __launch_bounds__(256) score_mma_kernel(
    const __nv_bfloat16* __restrict__ khi_, const __nv_bfloat16* __restrict__ klo_,
    const __nv_bfloat16* __restrict__ qhi_, const __nv_bfloat16* __restrict__ qlo_,
    float* __restrict__ srp, float* __restrict__ sip)
{
    extern __shared__ char smc[];
    const uint32_t smem_base = (uint32_t)__cvta_generic_to_shared(smc);
    const int tid = threadIdx.x, wid = tid >> 5, lane = tid & 31;
    const int m0 = blockIdx.x * 128, n0 = blockIdx.y * 128;
    const int b = blockIdx.z >> 5, sl = blockIdx.z & 31;
    const int warp_m = (wid >> 1) * 32, warp_n = (wid & 1) * 64;

    const size_t PL = (size_t)256 * 16384;
    const __nv_bfloat16* srcs[8] = {
        khi_ + (size_t)(b*2+0)*PL + (size_t)m0*16384,
        klo_ + (size_t)(b*2+0)*PL + (size_t)m0*16384,
        khi_ + (size_t)(b*2+1)*PL + (size_t)m0*16384,
        klo_ + (size_t)(b*2+1)*PL + (size_t)m0*16384,
        qhi_ + (size_t)(b*2+0)*PL + (size_t)n0*16384,
        qlo_ + (size_t)(b*2+0)*PL + (size_t)n0*16384,
        qhi_ + (size_t)(b*2+1)*PL + (size_t)n0*16384,
        qlo_ + (size_t)(b*2+1)*PL + (size_t)n0*16384
    };

    float acc[2][2][8][4];
    #pragma unroll
    for (int p = 0; p < 2; p++)
        #pragma unroll
        for (int fm = 0; fm < 2; fm++)
            #pragma unroll
            for (int fn = 0; fn < 8; fn++)
                #pragma unroll
                for (int u = 0; u < 4; u++) acc[p][fm][fn][u] = 0.f;

    const int a_row = (lane & 7) + ((lane >> 3) & 1) * 8;
    const int a_uoff = lane >> 4;
    const int b_row = (lane & 7) + ((lane >> 4) << 3);
    const int b_uoff = (lane >> 3) & 1;

    const int kbase = sl * 512;
    auto issueS = [&](int ch, int d) {
        const int k0 = kbase + ch*16;
        #pragma unroll
        for (int i = 0; i < 8; i++) {
            int idx = tid + i*256;
            int t = idx >> 8, rem = idx & 255;
            int row = rem >> 1, u = rem & 1;
            CPA16(smem_base + d*49152 + t*6144 + row*48 + u*16,
                  srcs[t] + (size_t)row*16384 + k0 + u*8);
        }
        CPA_COMMIT();
    };

    issueS(0, 0);
    for (int ch = 0; ch < 32; ch++) {
        if (ch < 31) { issueS(ch+1, (ch+1) & 1); CPA_WAIT(1); }
        else         { CPA_WAIT(0); }
        __syncthreads();
        const uint32_t cb = smem_base + (ch & 1)*49152;

        uint32_t afr[4][2][4];
        #pragma unroll
        for (int t = 0; t < 4; t++)
            #pragma unroll
            for (int fm = 0; fm < 2; fm++)
                ldm4(afr[t][fm], cb + t*6144
                     + (warp_m + fm*16 + a_row)*48 + a_uoff*16);
        uint32_t nKI[2][2][4];
        #pragma unroll
        for (int hl = 0; hl < 2; hl++)
            #pragma unroll
            for (int fm = 0; fm < 2; fm++)
                #pragma unroll
                for (int u = 0; u < 4; u++)
                    nKI[hl][fm][u] = afr[2+hl][fm][u] ^ 0x80008000u;

        #pragma unroll
        for (int qop = 0; qop < 4; qop++) {
            uint32_t bfr[8][2];
            #pragma unroll
            for (int pn = 0; pn < 4; pn++) {
                uint32_t r[4];
                ldm4(r, cb + (4+qop)*6144
                     + (warp_n + pn*16 + b_row)*48 + b_uoff*16);
                bfr[2*pn+0][0] = r[0]; bfr[2*pn+0][1] = r[1];
                bfr[2*pn+1][0] = r[2]; bfr[2*pn+1][1] = r[3];
            }
            #pragma unroll
            for (int fm = 0; fm < 2; fm++)
                #pragma unroll
                for (int fn = 0; fn < 8; fn++) {
                    uint32_t b0 = bfr[fn][0], b1 = bfr[fn][1];
                    if (qop == 0) {
                        mma16816(acc[0][fm][fn], afr[0][fm], b0, b1);
                        mma16816(acc[0][fm][fn], afr[1][fm], b0, b1);
                        mma16816(acc[1][fm][fn], nKI[0][fm], b0, b1);
                        mma16816(acc[1][fm][fn], nKI[1][fm], b0, b1);
                    } else if (qop == 1) {
                        mma16816(acc[0][fm][fn], afr[0][fm], b0, b1);
                        mma16816(acc[1][fm][fn], nKI[0][fm], b0, b1);
                    } else if (qop == 2) {
                        mma16816(acc[0][fm][fn], afr[2][fm], b0, b1);
                        mma16816(acc[0][fm][fn], afr[3][fm], b0, b1);
                        mma16816(acc[1][fm][fn], afr[0][fm], b0, b1);
                        mma16816(acc[1][fm][fn], afr[1][fm], b0, b1);
                    } else {
                        mma16816(acc[0][fm][fn], afr[2][fm], b0, b1);
                        mma16816(acc[1][fm][fn], afr[0][fm], b0, b1);
                    }
                }
        }
        __syncthreads();
    }

    const int rl = lane >> 2, cl = (lane & 3) * 2;
    #pragma unroll
    for (int fm = 0; fm < 2; fm++)
        #pragma unroll
        for (int fn = 0; fn < 8; fn++) {
            int m = m0 + warp_m + fm*16 + rl;
            int n = n0 + warp_n + fn*8 + cl;
            size_t off = (((size_t)sl*2 + b)*256 + m)*256 + n;
            float* c0 = acc[0][fm][fn];
            float* c1 = acc[1][fm][fn];
            *(float2*)(srp + off)         = make_float2(c0[0], c0[1]);
            *(float2*)(srp + off + 8*256) = make_float2(c0[2], c0[3]);
            *(float2*)(sip + off)         = make_float2(c1[0], c1[1]);
            *(float2*)(sip + off + 8*256) = make_float2(c1[2], c1[3]);
        }
}

// ---------------- softmax over query axis n, emits bf16 hi/lo --------------------
__global__ void __launch_bounds__(256) softmax_kernel(const float* __restrict__ srp,
                                                      const float* __restrict__ sip,
                                                      __nv_bfloat16* __restrict__ ahi,
                                                      __nv_bfloat16* __restrict__ alo)
{
    __shared__ float red[256];
    const int bm = blockIdx.x;
    const int b = bm >> 8, m = bm & 255;
    const int n = threadIdx.x;
    float sr = 0.f, si = 0.f;
    for (int sl = 0; sl < KSLICES; sl++) {
        size_t off = (((size_t)sl*2 + b)*256 + m)*256 + n;
        sr += srp[off]; si += sip[off];
    }
    float z = sqrtf(sr*sr + si*si);
    red[n] = z; __syncthreads();
    for (int st = 128; st > 0; st >>= 1) {
        if (n < st) red[n] = fmaxf(red[n], red[n+st]);
        __syncthreads();
    }
    float mx = red[0]; __syncthreads();
    float e = expf(z - mx);
    red[n] = e; __syncthreads();
    for (int st = 128; st > 0; st >>= 1) {
        if (n < st) red[n] += red[n+st];
        __syncthreads();
    }
    float a = e / red[0];
    float h = bf_hi(a);
    size_t off = ((size_t)b*256 + m)*256 + n;
    ahi[off] = __float2bfloat16_rn(h);
    alo[off] = __float2bfloat16_rn(a - h);
}

// ---------------- time-branch output (mma.sync split-3) --------------------------
__global__ void __launch_bounds__(256) out_time_mma_kernel(
    const __nv_bfloat16* __restrict__ vhi, const __nv_bfloat16* __restrict__ vlo,
    const __nv_bfloat16* __restrict__ ahi, const __nv_bfloat16* __restrict__ alo,
    float* __restrict__ out)
{
    __shared__ __align__(16) char sm[37888];
    const uint32_t sb = (uint32_t)__cvta_generic_to_shared(sm);
    const int tid = threadIdx.x, wid = tid >> 5, lane = tid & 31;
    const int r0 = blockIdx.x*128, n0 = blockIdx.y*128, b = blockIdx.z;
    const int warp_m = (wid >> 1) * 32, warp_n = (wid & 1) * 64;

    float acc[2][8][4];
    #pragma unroll
    for (int fm = 0; fm < 2; fm++)
        #pragma unroll
        for (int fn = 0; fn < 8; fn++)
            #pragma unroll
            for (int u = 0; u < 4; u++) acc[fm][fn][u] = 0.f;

    const int a_row = (lane & 7) + ((lane >> 3) & 1) * 8;
    const int a_u   = lane >> 4;
    const int bt_row = (lane & 7) + ((lane >> 3) & 1) * 8;
    const int bt_c   = (lane >> 4) * 8;

    for (int ch = 0; ch < 8; ch++) {
        const int m0c = ch*32;
        __syncthreads();
        #pragma unroll
        for (int i = 0; i < 4; i++) {
            int idx = tid + i*256;
            int hl = idx >> 9, rem = idx & 511;
            int row = rem >> 2, u = rem & 3;
            uint4 v = *(const uint4*)((hl ? vlo : vhi)
                        + (size_t)(b*32768 + r0 + row)*256 + m0c + u*8);
            *(uint4*)(sm + hl*10240 + row*80 + u*16) = v;
        }
        #pragma unroll
        for (int i = 0; i < 4; i++) {
            int idx = tid + i*256;
            int hl = idx >> 9, rem = idx & 511;
            int kk = rem >> 4, u = rem & 15;
            uint4 v = *(const uint4*)((hl ? alo : ahi)
                        + (size_t)(b*256 + m0c + kk)*256 + n0 + u*8);
            *(uint4*)(sm + 20480 + hl*8704 + kk*272 + u*16) = v;
        }
        __syncthreads();
        #pragma unroll
        for (int ks = 0; ks < 2; ks++) {
            uint32_t Vf[2][2][4];
            #pragma unroll
            for (int hl = 0; hl < 2; hl++)
                #pragma unroll
                for (int fm = 0; fm < 2; fm++)
                    ldm4(Vf[hl][fm], sb + hl*10240
                         + (warp_m + fm*16 + a_row)*80 + (ks*2 + a_u)*16);
            uint32_t Af[2][8][2];
            #pragma unroll
            for (int hl = 0; hl < 2; hl++)
                #pragma unroll
                for (int fn2 = 0; fn2 < 4; fn2++) {
                    uint32_t r[4];
                    ldm4t(r, sb + 20480 + hl*8704
                          + (ks*16 + bt_row)*272 + (warp_n + fn2*16 + bt_c)*2);
                    Af[hl][2*fn2+0][0] = r[0]; Af[hl][2*fn2+0][1] = r[1];
                    Af[hl][2*fn2+1][0] = r[2]; Af[hl][2*fn2+1][1] = r[3];
                }
            #pragma unroll
            for (int fm = 0; fm < 2; fm++)
                #pragma unroll
                for (int fn = 0; fn < 8; fn++) {
                    mma16816(acc[fm][fn], Vf[0][fm], Af[0][fn][0], Af[0][fn][1]);
                    mma16816(acc[fm][fn], Vf[0][fm], Af[1][fn][0], Af[1][fn][1]);
                    mma16816(acc[fm][fn], Vf[1][fm], Af[0][fn][0], Af[0][fn][1]);
                }
        }
    }
    const int rl = lane >> 2, cl = (lane & 3) * 2;
    #pragma unroll
    for (int fm = 0; fm < 2; fm++)
        #pragma unroll
        for (int fn = 0; fn < 8; fn++) {
            int r = r0 + warp_m + fm*16 + rl;
            int n = n0 + warp_n + fn*8 + cl;
            float* c4 = acc[fm][fn];
            *(float2*)(out + (size_t)(b*32768 + r)*256 + n)     = make_float2(c4[0], c4[1]);
            *(float2*)(out + (size_t)(b*32768 + r + 8)*256 + n) = make_float2(c4[2], c4[3]);
        }
}

// ---------------- freq-branch output (mma.sync split-3, accumulate) --------------
__global__ void __launch_bounds__(256) out_freq_mma_kernel(
    const __nv_bfloat16* __restrict__ vhi, const __nv_bfloat16* __restrict__ vlo,
    const __nv_bfloat16* __restrict__ ahi, const __nv_bfloat16* __restrict__ alo,
    float* __restrict__ out)
{
    __shared__ __align__(16) char sm[34816];
    const uint32_t sb = (uint32_t)__cvta_generic_to_shared(sm);
    const int tid = threadIdx.x, wid = tid >> 5, lane = tid & 31;
    const int f0 = (blockIdx.x >> 1)*128, t0 = (blockIdx.x & 1)*128;
    const int plane = blockIdx.y, b = plane >> 7;
    const int warp_f = (wid >> 1) * 32, warp_t = (wid & 1) * 64;
    const size_t vbase = (size_t)plane * SPAT;

    float acc[2][8][4];
    #pragma unroll
    for (int fm = 0; fm < 2; fm++)
        #pragma unroll
        for (int fn = 0; fn < 8; fn++)
            #pragma unroll
            for (int u = 0; u < 4; u++) acc[fm][fn][u] = 0.f;

    const int at_row = (lane & 7) + ((lane >> 4) << 3);
    const int at_c   = ((lane >> 3) & 1) * 8;
    const int bt_row = (lane & 7) + ((lane >> 3) & 1) * 8;
    const int bt_c   = (lane >> 4) * 8;

    for (int ch = 0; ch < 8; ch++) {
        const int m0c = ch*32;
        __syncthreads();
        #pragma unroll
        for (int i = 0; i < 4; i++) {
            int idx = tid + i*256;
            int hl = idx >> 9, rem = idx & 511;
            int kk = rem >> 4, u = rem & 15;
            uint4 v = *(const uint4*)((hl ? alo : ahi)
                        + (size_t)(b*256 + m0c + kk)*256 + f0 + u*8);
            *(uint4*)(sm + hl*8704 + kk*272 + u*16) = v;
        }
        #pragma unroll
        for (int i = 0; i < 4; i++) {
            int idx = tid + i*256;
            int hl = idx >> 9, rem = idx & 511;
            int kk = rem >> 4, u = rem & 15;
            uint4 v = *(const uint4*)((hl ? vlo : vhi)
                        + vbase + (size_t)(m0c + kk)*256 + t0 + u*8);
            *(uint4*)(sm + 17408 + hl*8704 + kk*272 + u*16) = v;
        }
        __syncthreads();
        #pragma unroll
        for (int ks = 0; ks < 2; ks++) {
            uint32_t Afr[2][2][4];
            #pragma unroll
            for (int hl = 0; hl < 2; hl++)
                #pragma unroll
                for (int fm = 0; fm < 2; fm++)
                    ldm4t(Afr[hl][fm], sb + hl*8704
                          + (ks*16 + at_row)*272 + (warp_f + fm*16 + at_c)*2);
            uint32_t Vfr[2][8][2];
            #pragma unroll
            for (int hl = 0; hl < 2; hl++)
                #pragma unroll
                for (int fn2 = 0; fn2 < 4; fn2++) {
                    uint32_t r[4];
                    ldm4t(r, sb + 17408 + hl*8704
                          + (ks*16 + bt_row)*272 + (warp_t + fn2*16 + bt_c)*2);
                    Vfr[hl][2*fn2+0][0] = r[0]; Vfr[hl][2*fn2+0][1] = r[1];
                    Vfr[hl][2*fn2+1][0] = r[2]; Vfr[hl][2*fn2+1][1] = r[3];
                }
            #pragma unroll
            for (int fm = 0; fm < 2; fm++)
                #pragma unroll
                for (int fn = 0; fn < 8; fn++) {
                    mma16816(acc[fm][fn], Afr[0][fm], Vfr[0][fn][0], Vfr[0][fn][1]);
                    mma16816(acc[fm][fn], Afr[0][fm], Vfr[1][fn][0], Vfr[1][fn][1]);
                    mma16816(acc[fm][fn], Afr[1][fm], Vfr[0][fn][0], Vfr[0][fn][1]);
                }
        }
    }
    const int rl = lane >> 2, cl = (lane & 3) * 2;
    #pragma unroll
    for (int fm = 0; fm < 2; fm++)
        #pragma unroll
        for (int fn = 0; fn < 8; fn++) {
            int f = f0 + warp_f + fm*16 + rl;
            int t = t0 + warp_t + fn*8 + cl;
            float* c4 = acc[fm][fn];
            float* d0 = out + vbase + (size_t)f*256 + t;
            float* d1 = out + vbase + (size_t)(f + 8)*256 + t;
            float2 o0 = *(float2*)d0, o1 = *(float2*)d1;
            o0.x += c4[0]; o0.y += c4[1];
            o1.x += c4[2]; o1.y += c4[3];
            *(float2*)d0 = o0; *(float2*)d1 = o1;
        }
}

// ---------------- host launch ----------------------------------------------------
extern "C" void kernel_launch(void* const* d_in, const int* in_sizes, int n_in,
                              void* d_out, int out_size)
{
    const float* P    = (const float*)d_in[0];
    const float* Q    = (const float*)d_in[1];
    const float* W    = (const float*)d_in[2];
    // d_in[3] = bias: cancels exactly under BN mean subtraction -> unused
    const float* g    = (const float*)d_in[4];
    const float* beta = (const float*)d_in[5];
    float* out = (float*)d_out;

    float *qp, *kp, *vp, *srp, *sip, *scp, *shp, *partp;
    __nv_bfloat16 *qhi, *qlo, *khi, *klo, *vhi, *vlo, *pshi, *pslo, *qshi, *qslo,
                  *ahip, *alop, *wcp;
    cudaGetSymbolAddress((void**)&qp,  g_q);
    cudaGetSymbolAddress((void**)&kp,  g_k);
    cudaGetSymbolAddress((void**)&vp,  g_v);
    cudaGetSymbolAddress((void**)&qhi, g_qhi);
    cudaGetSymbolAddress((void**)&qlo, g_qlo);
    cudaGetSymbolAddress((void**)&khi, g_khi);
    cudaGetSymbolAddress((void**)&klo, g_klo);
    cudaGetSymbolAddress((void**)&vhi, g_vhi);
    cudaGetSymbolAddress((void**)&vlo, g_vlo);
    cudaGetSymbolAddress((void**)&pshi, g_pshi);
    cudaGetSymbolAddress((void**)&pslo, g_pslo);
    cudaGetSymbolAddress((void**)&qshi, g_qshi);
    cudaGetSymbolAddress((void**)&qslo, g_qslo);
    cudaGetSymbolAddress((void**)&ahip, g_ahi);
    cudaGetSymbolAddress((void**)&alop, g_alo);
    cudaGetSymbolAddress((void**)&wcp, g_wc);
    cudaGetSymbolAddress((void**)&partp, g_part);
    cudaGetSymbolAddress((void**)&srp, g_srp);
    cudaGetSymbolAddress((void**)&sip, g_sip);
    cudaGetSymbolAddress((void**)&scp, g_scale6);
    cudaGetSymbolAddress((void**)&shp, g_shift6);

    cudaFuncSetAttribute(conv_mma_kernel, cudaFuncAttributeMaxDynamicSharedMemorySize, CONV2_SMEM);
    cudaFuncSetAttribute(score_mma_kernel, cudaFuncAttributeMaxDynamicSharedMemorySize, SC2_SMEM);

    // side stream + events (created once; per-call work is identical & deterministic)
    static cudaStream_t sside = nullptr;
    static cudaEvent_t ev[8];
    if (sside == nullptr) {
        cudaStreamCreateWithFlags(&sside, cudaStreamNonBlocking);
        for (int i = 0; i < 8; i++)
            cudaEventCreateWithFlags(&ev[i], cudaEventDisableTiming);
    }

    // one-time prep (main/legacy stream)
    split_kernel<<<16384, 256>>>(P, pshi, pslo);
    split_kernel<<<16384, 256>>>(Q, qshi, qslo);
    wcomb_kernel<<<dim3(64, 6), 256>>>(W, wcp);

    // conv on main; stats+convert forked onto side stream so next conv overlaps
    auto conv_fork = [&](const __nv_bfloat16* xhi, const __nv_bfloat16* xlo,
                         int j, float* Y, int chain, int evi) {
        float* part = partp + (size_t)chain*262144;
        conv_mma_kernel<<<dim3(512, 2), 256, CONV2_SMEM>>>(
            xhi, xlo, wcp + (size_t)j*32768, Y, part);
        cudaEventRecord(ev[evi], 0);
        cudaStreamWaitEvent(sside, ev[evi], 0);
        stats_reduce_kernel<<<128, 256, 0, sside>>>(part, g, beta, j, scp, shp);
    };

    // ---- time branch ----
    conv_fork(qshi, qslo, 0, qp, 0, 0);
    convert_T_kernel<<<dim3(8, 8, 256), 256, 0, sside>>>(qp, qhi, qlo, scp, shp, 0);
    conv_fork(pshi, pslo, 1, kp, 1, 1);
    convert_T_kernel<<<dim3(8, 8, 256), 256, 0, sside>>>(kp, khi, klo, scp, shp, 1);
    conv_fork(pshi, pslo, 2, vp, 2, 2);
    vconvert_kernel<<<16384, 256, 0, sside>>>(vp, vhi, vlo, scp, shp, 2);
    cudaEventRecord(ev[6], sside);
    cudaStreamWaitEvent(0, ev[6], 0);
    score_mma_kernel<<<dim3(2, 2, 64), 256, SC2_SMEM>>>(khi, klo, qhi, qlo, srp, sip);
    softmax_kernel<<<512, 256>>>(srp, sip, ahip, alop);
    out_time_mma_kernel<<<dim3(256, 2, 2), 256>>>(vhi, vlo, ahip, alop, out);

    // ---- freq branch ----
    conv_fork(qshi, qslo, 3, qp, 0, 3);
    convert_noT_kernel<<<dim3(32, 256), 256, 0, sside>>>(qp, qhi, qlo, scp, shp, 3);
    conv_fork(pshi, pslo, 4, kp, 1, 4);
    convert_noT_kernel<<<dim3(32, 256), 256, 0, sside>>>(kp, khi, klo, scp, shp, 4);
    conv_fork(pshi, pslo, 5, vp, 2, 5);
    vconvert_kernel<<<16384, 256, 0, sside>>>(vp, vhi, vlo, scp, shp, 5);
    cudaEventRecord(ev[7], sside);
    cudaStreamWaitEvent(0, ev[7], 0);
    score_mma_kernel<<<dim3(2, 2, 64), 256, SC2_SMEM>>>(khi, klo, qhi, qlo, srp, sip);
    softmax_kernel<<<512, 256>>>(srp, sip, ahip, alop);
    out_freq_mma_kernel<<<dim3(4, 256), 256>>>(vhi, vlo, ahip, alop, out);
}